// round 2
// baseline (speedup 1.0000x reference)
#include <cuda_runtime.h>
#include <cuda_bf16.h>
#include <math.h>

// ---------------------------------------------------------------------------
// CustomEncoderLayer: B=8, S=1024, D_MODEL=1024, N_HEAD=16, D_HEAD=64, D_FF=4096
// fp32 throughout. Round 1: correct baseline — fp32 tiled SGEMMs + flash attn.
// ---------------------------------------------------------------------------

#define BATCH   8
#define SEQ     1024
#define DMODEL  1024
#define NHEAD   16
#define DHEAD   64
#define DFF     4096
#define NTOK    (BATCH * SEQ)          // 8192
#define LN_EPS  1e-5f

// ------------------------- scratch (static device) -------------------------
__device__ float g_x   [NTOK * DMODEL];   // LN1 output
__device__ float g_q   [NTOK * DMODEL];
__device__ float g_k   [NTOK * DMODEL];
__device__ float g_v   [NTOK * DMODEL];
__device__ float g_ctx [NTOK * DMODEL];
__device__ float g_y   [NTOK * DMODEL];   // LN2 output
__device__ float g_h   [NTOK * DFF];      // FFN hidden

// ------------------------------- LayerNorm ---------------------------------
__global__ __launch_bounds__(256) void ln_kernel(
    const float* __restrict__ X, const float* __restrict__ gamma,
    const float* __restrict__ beta, float* __restrict__ Y)
{
    __shared__ float red[8];
    __shared__ float sh_mu, sh_rstd;
    const int row = blockIdx.x;
    const int tid = threadIdx.x;

    const float4* xr = (const float4*)(X + (size_t)row * DMODEL);
    float4 v = xr[tid];

    float s = v.x + v.y + v.z + v.w;
    #pragma unroll
    for (int o = 16; o; o >>= 1) s += __shfl_xor_sync(0xffffffffu, s, o);
    if ((tid & 31) == 0) red[tid >> 5] = s;
    __syncthreads();
    if (tid == 0) {
        float t = 0.f;
        #pragma unroll
        for (int i = 0; i < 8; i++) t += red[i];
        sh_mu = t * (1.0f / DMODEL);
    }
    __syncthreads();
    const float mu = sh_mu;

    float4 d = make_float4(v.x - mu, v.y - mu, v.z - mu, v.w - mu);
    float sq = d.x*d.x + d.y*d.y + d.z*d.z + d.w*d.w;
    #pragma unroll
    for (int o = 16; o; o >>= 1) sq += __shfl_xor_sync(0xffffffffu, sq, o);
    __syncthreads();                         // protect red[] reuse
    if ((tid & 31) == 0) red[tid >> 5] = sq;
    __syncthreads();
    if (tid == 0) {
        float t = 0.f;
        #pragma unroll
        for (int i = 0; i < 8; i++) t += red[i];
        sh_rstd = rsqrtf(t * (1.0f / DMODEL) + LN_EPS);
    }
    __syncthreads();
    const float rstd = sh_rstd;

    float4 gv = ((const float4*)gamma)[tid];
    float4 bv = ((const float4*)beta)[tid];
    float4 o;
    o.x = d.x * rstd * gv.x + bv.x;
    o.y = d.y * rstd * gv.y + bv.y;
    o.z = d.z * rstd * gv.z + bv.z;
    o.w = d.w * rstd * gv.w + bv.w;
    ((float4*)(Y + (size_t)row * DMODEL))[tid] = o;
}

// ------------------------------ tiled SGEMM --------------------------------
// C[M,N] = A[M,K] @ B[K,N] + bias[N]  (+ res)  (relu)
// BM=BN=128, BK=8, TM=TN=8, 256 threads, double-buffered smem.
template<bool RELU, bool RES>
__global__ __launch_bounds__(256, 2) void sgemm_kernel(
    const float* __restrict__ A, const float* __restrict__ B,
    const float* __restrict__ bias, const float* __restrict__ res,
    float* __restrict__ C, int M, int N, int K)
{
    const int BM = 128, BN = 128, BK = 8, TM = 8, TN = 8;
    __shared__ float As[2][BK][BM];
    __shared__ float Bs[2][BK][BN];

    const int tid = threadIdx.x;
    const int bx = blockIdx.x, by = blockIdx.y;

    const float* Ab = A + (size_t)by * BM * K;
    const float* Bb = B + (size_t)bx * BN;

    const int innerRowA = tid >> 1;            // 0..127
    const int innerColA = (tid & 1) * 4;       // 0 or 4
    const int innerRowB = tid >> 5;            // 0..7
    const int innerColB = (tid & 31) * 4;      // 0..124

    const int tr = (tid >> 4) * TM;            // 0..120
    const int tc = (tid & 15) * TN;            // 0..120

    float acc[TM][TN];
    #pragma unroll
    for (int i = 0; i < TM; i++)
        #pragma unroll
        for (int j = 0; j < TN; j++) acc[i][j] = 0.f;

    // prologue: load tile 0 into buffer 0
    {
        float4 a = *(const float4*)(Ab + (size_t)innerRowA * K + innerColA);
        As[0][innerColA + 0][innerRowA] = a.x;
        As[0][innerColA + 1][innerRowA] = a.y;
        As[0][innerColA + 2][innerRowA] = a.z;
        As[0][innerColA + 3][innerRowA] = a.w;
        *(float4*)&Bs[0][innerRowB][innerColB] =
            *(const float4*)(Bb + (size_t)innerRowB * N + innerColB);
    }
    __syncthreads();

    int buf = 0;
    for (int k0 = 0; k0 < K; k0 += BK) {
        const int nxt = k0 + BK;
        if (nxt < K) {
            float4 a = *(const float4*)(Ab + (size_t)innerRowA * K + nxt + innerColA);
            const int nb = buf ^ 1;
            As[nb][innerColA + 0][innerRowA] = a.x;
            As[nb][innerColA + 1][innerRowA] = a.y;
            As[nb][innerColA + 2][innerRowA] = a.z;
            As[nb][innerColA + 3][innerRowA] = a.w;
            *(float4*)&Bs[nb][innerRowB][innerColB] =
                *(const float4*)(Bb + (size_t)(nxt + innerRowB) * N + innerColB);
        }
        #pragma unroll
        for (int kk = 0; kk < BK; kk++) {
            float4 m0 = *(const float4*)&As[buf][kk][tr];
            float4 m1 = *(const float4*)&As[buf][kk][tr + 4];
            float4 n0 = *(const float4*)&Bs[buf][kk][tc];
            float4 n1 = *(const float4*)&Bs[buf][kk][tc + 4];
            float regM[TM] = {m0.x, m0.y, m0.z, m0.w, m1.x, m1.y, m1.z, m1.w};
            float regN[TN] = {n0.x, n0.y, n0.z, n0.w, n1.x, n1.y, n1.z, n1.w};
            #pragma unroll
            for (int i = 0; i < TM; i++)
                #pragma unroll
                for (int j = 0; j < TN; j++)
                    acc[i][j] = fmaf(regM[i], regN[j], acc[i][j]);
        }
        __syncthreads();
        buf ^= 1;
    }

    // epilogue
    const float* biasb = bias + (size_t)bx * BN;
    float* Cb = C + (size_t)(by * BM) * N + (size_t)bx * BN;
    const float* Rb = RES ? (res + (size_t)(by * BM) * N + (size_t)bx * BN) : nullptr;

    #pragma unroll
    for (int i = 0; i < TM; i++) {
        const int r = tr + i;
        #pragma unroll
        for (int j = 0; j < TN; j += 4) {
            float4 bv = *(const float4*)(biasb + tc + j);
            float4 o;
            o.x = acc[i][j + 0] + bv.x;
            o.y = acc[i][j + 1] + bv.y;
            o.z = acc[i][j + 2] + bv.z;
            o.w = acc[i][j + 3] + bv.w;
            if (RES) {
                float4 rv = *(const float4*)(Rb + (size_t)r * N + tc + j);
                o.x += rv.x; o.y += rv.y; o.z += rv.z; o.w += rv.w;
            }
            if (RELU) {
                o.x = fmaxf(o.x, 0.f); o.y = fmaxf(o.y, 0.f);
                o.z = fmaxf(o.z, 0.f); o.w = fmaxf(o.w, 0.f);
            }
            *(float4*)(Cb + (size_t)r * N + tc + j) = o;
        }
    }
}

// ---------------------------- flash attention ------------------------------
// grid (S/128, NHEAD, BATCH), block 128. Thread t owns query row blockIdx.x*128+t.
// Layouts: Q/K/V/O are [B, S, NHEAD*DHEAD] (head h at column offset h*64).
__global__ __launch_bounds__(128) void flash_attn_kernel(
    const float* __restrict__ Q, const float* __restrict__ K,
    const float* __restrict__ V, float* __restrict__ O)
{
    const int TK = 64;
    __shared__ float Ks[TK][DHEAD];
    __shared__ float Vs[TK][DHEAD];

    const int tid = threadIdx.x;
    const int b = blockIdx.z, h = blockIdx.y;
    const int s = blockIdx.x * 128 + tid;

    const float* qp = Q + ((size_t)(b * SEQ + s)) * DMODEL + h * DHEAD;
    float q[DHEAD], acc[DHEAD];
    #pragma unroll
    for (int d = 0; d < DHEAD; d++) { q[d] = qp[d] * 0.125f; acc[d] = 0.f; }

    float m = -1e30f, l = 0.f;
    const float* Kb = K + ((size_t)(b * SEQ)) * DMODEL + h * DHEAD;
    const float* Vb = V + ((size_t)(b * SEQ)) * DMODEL + h * DHEAD;

    for (int kt = 0; kt < SEQ; kt += TK) {
        // cooperative load: 64x64 floats = 1024 float4 = 8 per thread (each of K,V)
        #pragma unroll
        for (int i = 0; i < 8; i++) {
            const int f = tid + i * 128;
            const int r = f >> 4;
            const int c = (f & 15) * 4;
            *(float4*)&Ks[r][c] = *(const float4*)(Kb + (size_t)(kt + r) * DMODEL + c);
            *(float4*)&Vs[r][c] = *(const float4*)(Vb + (size_t)(kt + r) * DMODEL + c);
        }
        __syncthreads();

        #pragma unroll 2
        for (int j = 0; j < TK; j++) {
            float sdot = 0.f;
            #pragma unroll
            for (int d = 0; d < DHEAD; d++) sdot = fmaf(q[d], Ks[j][d], sdot);
            if (sdot > m) {
                const float alpha = __expf(m - sdot);
                l *= alpha;
                #pragma unroll
                for (int d = 0; d < DHEAD; d++) acc[d] *= alpha;
                m = sdot;
            }
            const float p = __expf(sdot - m);
            l += p;
            #pragma unroll
            for (int d = 0; d < DHEAD; d++) acc[d] = fmaf(p, Vs[j][d], acc[d]);
        }
        __syncthreads();
    }

    const float inv = 1.0f / l;
    float* op = O + ((size_t)(b * SEQ + s)) * DMODEL + h * DHEAD;
    #pragma unroll
    for (int d = 0; d < DHEAD; d++) op[d] = acc[d] * inv;
}

// ------------------------------- launcher ----------------------------------
extern "C" void kernel_launch(void* const* d_in, const int* in_sizes, int n_in,
                              void* d_out, int out_size)
{
    const float* src   = (const float*)d_in[0];
    const float* Wq    = (const float*)d_in[1];
    const float* bq    = (const float*)d_in[2];
    const float* Wk    = (const float*)d_in[3];
    const float* bk    = (const float*)d_in[4];
    const float* Wv    = (const float*)d_in[5];
    const float* bv    = (const float*)d_in[6];
    const float* Wo    = (const float*)d_in[7];
    const float* bo    = (const float*)d_in[8];
    const float* W1    = (const float*)d_in[9];
    const float* b1    = (const float*)d_in[10];
    const float* W2    = (const float*)d_in[11];
    const float* b2    = (const float*)d_in[12];
    const float* g1    = (const float*)d_in[13];
    const float* beta1 = (const float*)d_in[14];
    const float* g2    = (const float*)d_in[15];
    const float* beta2 = (const float*)d_in[16];
    float* out = (float*)d_out;

    float *x, *q, *k, *v, *ctx, *y, *hbuf;
    cudaGetSymbolAddress((void**)&x,    g_x);
    cudaGetSymbolAddress((void**)&q,    g_q);
    cudaGetSymbolAddress((void**)&k,    g_k);
    cudaGetSymbolAddress((void**)&v,    g_v);
    cudaGetSymbolAddress((void**)&ctx,  g_ctx);
    cudaGetSymbolAddress((void**)&y,    g_y);
    cudaGetSymbolAddress((void**)&hbuf, g_h);

    const dim3 blk256(256);
    const dim3 gD(DMODEL / 128, NTOK / 128);   // (8, 64)
    const dim3 gF(DFF / 128,    NTOK / 128);   // (32, 64)

    // 1) LN1
    ln_kernel<<<NTOK, blk256>>>(src, g1, beta1, x);

    // 2) QKV projections
    sgemm_kernel<false, false><<<gD, blk256>>>(x, Wq, bq, nullptr, q, NTOK, DMODEL, DMODEL);
    sgemm_kernel<false, false><<<gD, blk256>>>(x, Wk, bk, nullptr, k, NTOK, DMODEL, DMODEL);
    sgemm_kernel<false, false><<<gD, blk256>>>(x, Wv, bv, nullptr, v, NTOK, DMODEL, DMODEL);

    // 3) attention
    dim3 gA(SEQ / 128, NHEAD, BATCH);
    flash_attn_kernel<<<gA, 128>>>(q, k, v, ctx);

    // 4) output projection + residual -> src2 (stored in d_out)
    sgemm_kernel<false, true><<<gD, blk256>>>(ctx, Wo, bo, src, out, NTOK, DMODEL, DMODEL);

    // 5) LN2
    ln_kernel<<<NTOK, blk256>>>(out, g2, beta2, y);

    // 6) FFN up + ReLU
    sgemm_kernel<true, false><<<gF, blk256>>>(y, W1, b1, nullptr, hbuf, NTOK, DFF, DMODEL);

    // 7) FFN down + bias + residual (in-place on d_out)
    sgemm_kernel<false, true><<<gD, blk256>>>(hbuf, W2, b2, out, out, NTOK, DMODEL, DFF);
}

// round 5
// speedup vs baseline: 2.5259x; 2.5259x over previous
#include <cuda_runtime.h>
#include <cuda_bf16.h>
#include <math.h>
#include <stdint.h>

// ---------------------------------------------------------------------------
// CustomEncoderLayer on GB300 (sm_103 PTX target — no 'a' features).
// R4: GEMMs via mma.sync tf32 (m16n8k8) + cp.async double-buffered pipeline.
// ---------------------------------------------------------------------------

#define BATCH   8
#define SEQ     1024
#define DMODEL  1024
#define NHEAD   16
#define DHEAD   64
#define DFF     4096
#define NTOK    (BATCH * SEQ)          // 8192
#define LN_EPS  1e-5f

// ------------------------- scratch (static device) -------------------------
__device__ float g_x    [NTOK * DMODEL];        // LN1 out (tf32-rounded)
__device__ float g_qkv  [NTOK * 3 * DMODEL];    // fused q|k|v
__device__ float g_ctx  [NTOK * DMODEL];        // attention out (tf32-rounded)
__device__ float g_y    [NTOK * DMODEL];        // LN2 out (tf32-rounded)
__device__ float g_h    [NTOK * DFF];           // FFN hidden (tf32-rounded)
__device__ float g_wqkv [DMODEL * 3 * DMODEL];  // packed+rounded [K, 3N]
__device__ float g_bqkv [3 * DMODEL];
__device__ float g_wor  [DMODEL * DMODEL];      // rounded Wo [K,N]
__device__ float g_w1r  [DMODEL * DFF];
__device__ float g_w2r  [DFF * DMODEL];

// ------------------------------ helpers ------------------------------------
__device__ __forceinline__ float to_tf32(float x) {
    float r;
    asm("cvt.rna.tf32.f32 %0, %1;" : "=f"(r) : "f"(x));
    return r;
}

__device__ __forceinline__ void mma_tf32(float c[4], const uint32_t a[4], const uint32_t b[2]) {
    asm volatile(
        "mma.sync.aligned.m16n8k8.row.col.f32.tf32.tf32.f32 "
        "{%0,%1,%2,%3}, {%4,%5,%6,%7}, {%8,%9}, {%10,%11,%12,%13};"
        : "=f"(c[0]), "=f"(c[1]), "=f"(c[2]), "=f"(c[3])
        : "r"(a[0]), "r"(a[1]), "r"(a[2]), "r"(a[3]),
          "r"(b[0]), "r"(b[1]),
          "f"(c[0]), "f"(c[1]), "f"(c[2]), "f"(c[3]));
}

__device__ __forceinline__ uint32_t smem_u32(const void* p) {
    uint32_t a;
    asm("{ .reg .u64 t; cvta.to.shared.u64 t, %1; cvt.u32.u64 %0, t; }" : "=r"(a) : "l"(p));
    return a;
}

#define CP_ASYNC16(dst, src) \
    asm volatile("cp.async.cg.shared.global [%0], [%1], 16;" :: "r"(dst), "l"(src))
#define CP_COMMIT() asm volatile("cp.async.commit_group;" ::: "memory")
#define CP_WAIT(n)  asm volatile("cp.async.wait_group %0;" :: "n"(n) : "memory")

// ------------------------------ tf32 GEMM ----------------------------------
// C[M,N] = A[M,K] @ B[K,N] + bias (+res) (relu) (round-to-tf32 on store).
// A,B pre-rounded to tf32. BM=BN=128, BK=32, 256 thr, 8 warps (2m x 4n),
// warp tile 64x32, double-buffered cp.async.
#define APAD_STRIDE 36      // 32 + 4  -> A frag reads conflict-free
#define BPAD_STRIDE 136     // 128 + 8 -> B frag reads conflict-free
#define A_STAGE_FLOATS (128 * APAD_STRIDE)          // 4608
#define B_STAGE_FLOATS (32 * BPAD_STRIDE)           // 4352
#define STAGE_FLOATS   (A_STAGE_FLOATS + B_STAGE_FLOATS)  // 8960
#define GEMM_SMEM_BYTES (2 * STAGE_FLOATS * 4)      // 71680

template<bool RELU, bool RES, bool ROUND>
__global__ void __launch_bounds__(256, 2) mma_gemm_kernel(
    const float* __restrict__ A, const float* __restrict__ B,
    const float* __restrict__ bias, const float* __restrict__ res,
    float* __restrict__ C, int N, int K)
{
    extern __shared__ float smem[];
    const uint32_t sbase = smem_u32(smem);

    const int tid = threadIdx.x;
    const int wid = tid >> 5, lid = tid & 31;
    const int gID = lid >> 2, tg = lid & 3;
    const int warp_m = wid >> 2, warp_n = wid & 3;
    const int bx = blockIdx.x, by = blockIdx.y;
    const int KT = K >> 5;

    float acc[4][4][4];
    #pragma unroll
    for (int mt = 0; mt < 4; mt++)
        #pragma unroll
        for (int nt = 0; nt < 4; nt++)
            #pragma unroll
            for (int r = 0; r < 4; r++) acc[mt][nt][r] = 0.f;

    const float* Ag0 = A + (size_t)(by * 128) * K;
    const float* Bg0 = B + (size_t)(bx * 128);

    // stage loader: A tile 128x32 (1024 x 16B chunks), B tile 32x128 (1024 chunks)
    auto load_stage = [&](int s, int kt) {
        const uint32_t sA = sbase + (uint32_t)(s * STAGE_FLOATS) * 4u;
        const uint32_t sB = sA + A_STAGE_FLOATS * 4u;
        const float* Ag = Ag0 + kt * 32;
        const float* Bg = Bg0 + (size_t)(kt * 32) * N;
        #pragma unroll
        for (int i = 0; i < 4; i++) {
            const int idx = tid + i * 256;
            const int ar = idx >> 3, ac = (idx & 7) * 4;
            CP_ASYNC16(sA + (uint32_t)(ar * APAD_STRIDE + ac) * 4u,
                       Ag + (size_t)ar * K + ac);
            const int br = idx >> 5, bc = (idx & 31) * 4;
            CP_ASYNC16(sB + (uint32_t)(br * BPAD_STRIDE + bc) * 4u,
                       Bg + (size_t)br * N + bc);
        }
    };

    load_stage(0, 0);
    CP_COMMIT();

    for (int kt = 0; kt < KT; kt++) {
        if (kt + 1 < KT) {
            load_stage((kt + 1) & 1, kt + 1);
            CP_COMMIT();
            CP_WAIT(1);
        } else {
            CP_WAIT(0);
        }
        __syncthreads();

        const float* As_ = smem + (kt & 1) * STAGE_FLOATS;
        const float* Bs_ = As_ + A_STAGE_FLOATS;

        #pragma unroll
        for (int ks = 0; ks < 4; ks++) {
            const int kb = ks * 8;
            uint32_t afr[4][4];
            uint32_t bfr[4][2];
            #pragma unroll
            for (int mt = 0; mt < 4; mt++) {
                const float* ap = As_ + (warp_m * 64 + mt * 16 + gID) * APAD_STRIDE + kb + tg;
                afr[mt][0] = __float_as_uint(ap[0]);
                afr[mt][1] = __float_as_uint(ap[8 * APAD_STRIDE]);
                afr[mt][2] = __float_as_uint(ap[4]);
                afr[mt][3] = __float_as_uint(ap[8 * APAD_STRIDE + 4]);
            }
            #pragma unroll
            for (int nt = 0; nt < 4; nt++) {
                const float* bp = Bs_ + (kb + tg) * BPAD_STRIDE + warp_n * 32 + nt * 8 + gID;
                bfr[nt][0] = __float_as_uint(bp[0]);
                bfr[nt][1] = __float_as_uint(bp[4 * BPAD_STRIDE]);
            }
            #pragma unroll
            for (int mt = 0; mt < 4; mt++)
                #pragma unroll
                for (int nt = 0; nt < 4; nt++)
                    mma_tf32(acc[mt][nt], afr[mt], bfr[nt]);
        }
        __syncthreads();
    }

    // epilogue
    const int row_base = by * 128 + warp_m * 64 + gID;
    const int col_base = bx * 128 + warp_n * 32 + 2 * tg;
    #pragma unroll
    for (int mt = 0; mt < 4; mt++) {
        const int r0 = row_base + mt * 16;
        const int r1 = r0 + 8;
        #pragma unroll
        for (int nt = 0; nt < 4; nt++) {
            const int c = col_base + nt * 8;
            const float2 bv = *(const float2*)(bias + c);
            float2 o0 = make_float2(acc[mt][nt][0] + bv.x, acc[mt][nt][1] + bv.y);
            float2 o1 = make_float2(acc[mt][nt][2] + bv.x, acc[mt][nt][3] + bv.y);
            if (RES) {
                const float2 q0 = *(const float2*)(res + (size_t)r0 * N + c);
                const float2 q1 = *(const float2*)(res + (size_t)r1 * N + c);
                o0.x += q0.x; o0.y += q0.y;
                o1.x += q1.x; o1.y += q1.y;
            }
            if (RELU) {
                o0.x = fmaxf(o0.x, 0.f); o0.y = fmaxf(o0.y, 0.f);
                o1.x = fmaxf(o1.x, 0.f); o1.y = fmaxf(o1.y, 0.f);
            }
            if (ROUND) {
                o0.x = to_tf32(o0.x); o0.y = to_tf32(o0.y);
                o1.x = to_tf32(o1.x); o1.y = to_tf32(o1.y);
            }
            *(float2*)(C + (size_t)r0 * N + c) = o0;
            *(float2*)(C + (size_t)r1 * N + c) = o1;
        }
    }
}

// --------------------------- weight pre-passes -----------------------------
__global__ __launch_bounds__(256) void pack_qkv_w_kernel(
    const float* __restrict__ wq, const float* __restrict__ wk,
    const float* __restrict__ wv, float* __restrict__ out)
{
    const int idx = blockIdx.x * 256 + threadIdx.x;   // over 1024*3072
    if (idx >= DMODEL * 3 * DMODEL) return;
    const int k = idx / (3 * DMODEL);
    const int c = idx - k * (3 * DMODEL);
    const float* src = (c < DMODEL) ? wq : (c < 2 * DMODEL ? wk : wv);
    const int cc = c & (DMODEL - 1);
    out[idx] = to_tf32(src[k * DMODEL + cc]);
}

__global__ __launch_bounds__(256) void pack_bias_kernel(
    const float* __restrict__ bq, const float* __restrict__ bk,
    const float* __restrict__ bv, float* __restrict__ out)
{
    const int c = blockIdx.x * 256 + threadIdx.x;
    if (c >= 3 * DMODEL) return;
    const float* src = (c < DMODEL) ? bq : (c < 2 * DMODEL ? bk : bv);
    out[c] = src[c & (DMODEL - 1)];
}

__global__ __launch_bounds__(256) void round_copy4_kernel(
    const float* __restrict__ in, float* __restrict__ out, int n4)
{
    const int i = blockIdx.x * 256 + threadIdx.x;
    if (i >= n4) return;
    float4 v = ((const float4*)in)[i];
    v.x = to_tf32(v.x); v.y = to_tf32(v.y);
    v.z = to_tf32(v.z); v.w = to_tf32(v.w);
    ((float4*)out)[i] = v;
}

// ------------------------------- LayerNorm ---------------------------------
template<bool ROUND>
__global__ __launch_bounds__(256) void ln_kernel(
    const float* __restrict__ X, const float* __restrict__ gamma,
    const float* __restrict__ beta, float* __restrict__ Y)
{
    __shared__ float red[8];
    __shared__ float sh_mu, sh_rstd;
    const int row = blockIdx.x;
    const int tid = threadIdx.x;

    const float4* xr = (const float4*)(X + (size_t)row * DMODEL);
    float4 v = xr[tid];

    float s = v.x + v.y + v.z + v.w;
    #pragma unroll
    for (int o = 16; o; o >>= 1) s += __shfl_xor_sync(0xffffffffu, s, o);
    if ((tid & 31) == 0) red[tid >> 5] = s;
    __syncthreads();
    if (tid == 0) {
        float t = 0.f;
        #pragma unroll
        for (int i = 0; i < 8; i++) t += red[i];
        sh_mu = t * (1.0f / DMODEL);
    }
    __syncthreads();
    const float mu = sh_mu;

    float4 d = make_float4(v.x - mu, v.y - mu, v.z - mu, v.w - mu);
    float sq = d.x*d.x + d.y*d.y + d.z*d.z + d.w*d.w;
    #pragma unroll
    for (int o = 16; o; o >>= 1) sq += __shfl_xor_sync(0xffffffffu, sq, o);
    __syncthreads();
    if ((tid & 31) == 0) red[tid >> 5] = sq;
    __syncthreads();
    if (tid == 0) {
        float t = 0.f;
        #pragma unroll
        for (int i = 0; i < 8; i++) t += red[i];
        sh_rstd = rsqrtf(t * (1.0f / DMODEL) + LN_EPS);
    }
    __syncthreads();
    const float rstd = sh_rstd;

    float4 gv = ((const float4*)gamma)[tid];
    float4 bv = ((const float4*)beta)[tid];
    float4 o;
    o.x = d.x * rstd * gv.x + bv.x;
    o.y = d.y * rstd * gv.y + bv.y;
    o.z = d.z * rstd * gv.z + bv.z;
    o.w = d.w * rstd * gv.w + bv.w;
    if (ROUND) {
        o.x = to_tf32(o.x); o.y = to_tf32(o.y);
        o.z = to_tf32(o.z); o.w = to_tf32(o.w);
    }
    ((float4*)(Y + (size_t)row * DMODEL))[tid] = o;
}

// ---------------------------- flash attention ------------------------------
// QKV fused layout: row stride 3*DMODEL; q at +0, k at +DMODEL, v at +2*DMODEL,
// head h at column offset h*DHEAD within each. Output ctx rounded to tf32.
#define QKV_LD (3 * DMODEL)

__global__ __launch_bounds__(128) void flash_attn_kernel(
    const float* __restrict__ QKV, float* __restrict__ O)
{
    const int TK = 64;
    __shared__ float Ks[TK][DHEAD];
    __shared__ float Vs[TK][DHEAD];

    const int tid = threadIdx.x;
    const int b = blockIdx.z, h = blockIdx.y;
    const int s = blockIdx.x * 128 + tid;

    const float* qp = QKV + (size_t)(b * SEQ + s) * QKV_LD + h * DHEAD;
    float q[DHEAD], acc[DHEAD];
    #pragma unroll
    for (int d = 0; d < DHEAD; d++) { q[d] = qp[d] * 0.125f; acc[d] = 0.f; }

    float m = -1e30f, l = 0.f;
    const float* Kb = QKV + (size_t)(b * SEQ) * QKV_LD + DMODEL + h * DHEAD;
    const float* Vb = Kb + DMODEL;

    for (int kt = 0; kt < SEQ; kt += TK) {
        #pragma unroll
        for (int i = 0; i < 8; i++) {
            const int f = tid + i * 128;
            const int r = f >> 4;
            const int c = (f & 15) * 4;
            *(float4*)&Ks[r][c] = *(const float4*)(Kb + (size_t)(kt + r) * QKV_LD + c);
            *(float4*)&Vs[r][c] = *(const float4*)(Vb + (size_t)(kt + r) * QKV_LD + c);
        }
        __syncthreads();

        #pragma unroll 2
        for (int j = 0; j < TK; j++) {
            float sdot = 0.f;
            #pragma unroll
            for (int d = 0; d < DHEAD; d++) sdot = fmaf(q[d], Ks[j][d], sdot);
            if (sdot > m) {
                const float alpha = __expf(m - sdot);
                l *= alpha;
                #pragma unroll
                for (int d = 0; d < DHEAD; d++) acc[d] *= alpha;
                m = sdot;
            }
            const float p = __expf(sdot - m);
            l += p;
            #pragma unroll
            for (int d = 0; d < DHEAD; d++) acc[d] = fmaf(p, Vs[j][d], acc[d]);
        }
        __syncthreads();
    }

    const float inv = 1.0f / l;
    float* op = O + (size_t)(b * SEQ + s) * DMODEL + h * DHEAD;
    #pragma unroll
    for (int d = 0; d < DHEAD; d++) op[d] = to_tf32(acc[d] * inv);
}

// ------------------------------- launcher ----------------------------------
extern "C" void kernel_launch(void* const* d_in, const int* in_sizes, int n_in,
                              void* d_out, int out_size)
{
    const float* src   = (const float*)d_in[0];
    const float* Wq    = (const float*)d_in[1];
    const float* bq    = (const float*)d_in[2];
    const float* Wk    = (const float*)d_in[3];
    const float* bk    = (const float*)d_in[4];
    const float* Wv    = (const float*)d_in[5];
    const float* bv    = (const float*)d_in[6];
    const float* Wo    = (const float*)d_in[7];
    const float* bo    = (const float*)d_in[8];
    const float* W1    = (const float*)d_in[9];
    const float* b1    = (const float*)d_in[10];
    const float* W2    = (const float*)d_in[11];
    const float* b2    = (const float*)d_in[12];
    const float* g1    = (const float*)d_in[13];
    const float* beta1 = (const float*)d_in[14];
    const float* g2    = (const float*)d_in[15];
    const float* beta2 = (const float*)d_in[16];
    float* out = (float*)d_out;

    float *x, *qkv, *ctx, *y, *hbuf, *wqkv, *bqkv, *wor, *w1r, *w2r;
    cudaGetSymbolAddress((void**)&x,    g_x);
    cudaGetSymbolAddress((void**)&qkv,  g_qkv);
    cudaGetSymbolAddress((void**)&ctx,  g_ctx);
    cudaGetSymbolAddress((void**)&y,    g_y);
    cudaGetSymbolAddress((void**)&hbuf, g_h);
    cudaGetSymbolAddress((void**)&wqkv, g_wqkv);
    cudaGetSymbolAddress((void**)&bqkv, g_bqkv);
    cudaGetSymbolAddress((void**)&wor,  g_wor);
    cudaGetSymbolAddress((void**)&w1r,  g_w1r);
    cudaGetSymbolAddress((void**)&w2r,  g_w2r);

    cudaFuncSetAttribute(mma_gemm_kernel<false,false,false>,
        cudaFuncAttributeMaxDynamicSharedMemorySize, GEMM_SMEM_BYTES);
    cudaFuncSetAttribute(mma_gemm_kernel<false,true,false>,
        cudaFuncAttributeMaxDynamicSharedMemorySize, GEMM_SMEM_BYTES);
    cudaFuncSetAttribute(mma_gemm_kernel<true,false,true>,
        cudaFuncAttributeMaxDynamicSharedMemorySize, GEMM_SMEM_BYTES);

    // 0) weight/bias pre-passes (round to tf32; pack QKV)
    pack_qkv_w_kernel<<<(DMODEL * 3 * DMODEL + 255) / 256, 256>>>(Wq, Wk, Wv, wqkv);
    pack_bias_kernel<<<(3 * DMODEL + 255) / 256, 256>>>(bq, bk, bv, bqkv);
    round_copy4_kernel<<<(DMODEL * DMODEL / 4 + 255) / 256, 256>>>(Wo, wor, DMODEL * DMODEL / 4);
    round_copy4_kernel<<<(DMODEL * DFF / 4 + 255) / 256, 256>>>(W1, w1r, DMODEL * DFF / 4);
    round_copy4_kernel<<<(DFF * DMODEL / 4 + 255) / 256, 256>>>(W2, w2r, DFF * DMODEL / 4);

    // 1) LN1 (tf32-rounded output)
    ln_kernel<true><<<NTOK, 256>>>(src, g1, beta1, x);

    // 2) fused QKV projection: [8192,1024] @ [1024,3072]
    {
        dim3 g(3 * DMODEL / 128, NTOK / 128);   // (24, 64)
        mma_gemm_kernel<false,false,false><<<g, 256, GEMM_SMEM_BYTES>>>(
            x, wqkv, bqkv, nullptr, qkv, 3 * DMODEL, DMODEL);
    }

    // 3) attention (ctx rounded)
    {
        dim3 g(SEQ / 128, NHEAD, BATCH);
        flash_attn_kernel<<<g, 128>>>(qkv, ctx);
    }

    // 4) output projection + residual -> d_out
    {
        dim3 g(DMODEL / 128, NTOK / 128);       // (8, 64)
        mma_gemm_kernel<false,true,false><<<g, 256, GEMM_SMEM_BYTES>>>(
            ctx, wor, bo, src, out, DMODEL, DMODEL);
    }

    // 5) LN2 (tf32-rounded output)
    ln_kernel<true><<<NTOK, 256>>>(out, g2, beta2, y);

    // 6) FFN up + ReLU (rounded store)
    {
        dim3 g(DFF / 128, NTOK / 128);          // (32, 64)
        mma_gemm_kernel<true,false,true><<<g, 256, GEMM_SMEM_BYTES>>>(
            y, w1r, b1, nullptr, hbuf, DFF, DMODEL);
    }

    // 7) FFN down + bias + residual (in-place on d_out)
    {
        dim3 g(DMODEL / 128, NTOK / 128);       // (8, 64)
        mma_gemm_kernel<false,true,false><<<g, 256, GEMM_SMEM_BYTES>>>(
            hbuf, w2r, b2, out, out, DMODEL, DFF);
    }
}

// round 9
// speedup vs baseline: 4.0716x; 1.6119x over previous
#include <cuda_runtime.h>
#include <cuda_bf16.h>
#include <math.h>
#include <stdint.h>

// ---------------------------------------------------------------------------
// CustomEncoderLayer on GB300 (sm_103 PTX target — no 'a' features).
// R6: GEMMs via mma.sync tf32 (R5) + NEW mma.sync tf32 flash attention.
// ---------------------------------------------------------------------------

#define BATCH   8
#define SEQ     1024
#define DMODEL  1024
#define NHEAD   16
#define DHEAD   64
#define DFF     4096
#define NTOK    (BATCH * SEQ)          // 8192
#define LN_EPS  1e-5f

// ------------------------- scratch (static device) -------------------------
__device__ float g_x    [NTOK * DMODEL];        // LN1 out (tf32-rounded)
__device__ float g_qkv  [NTOK * 3 * DMODEL];    // fused q|k|v
__device__ float g_ctx  [NTOK * DMODEL];        // attention out (tf32-rounded)
__device__ float g_y    [NTOK * DMODEL];        // LN2 out (tf32-rounded)
__device__ float g_h    [NTOK * DFF];           // FFN hidden (tf32-rounded)
__device__ float g_wqkv [DMODEL * 3 * DMODEL];  // packed+rounded [K, 3N]
__device__ float g_bqkv [3 * DMODEL];
__device__ float g_wor  [DMODEL * DMODEL];      // rounded Wo [K,N]
__device__ float g_w1r  [DMODEL * DFF];
__device__ float g_w2r  [DFF * DMODEL];

// ------------------------------ helpers ------------------------------------
__device__ __forceinline__ float to_tf32(float x) {
    float r;
    asm("cvt.rna.tf32.f32 %0, %1;" : "=f"(r) : "f"(x));
    return r;
}

__device__ __forceinline__ void mma_tf32(float c[4], const uint32_t a[4], const uint32_t b[2]) {
    asm volatile(
        "mma.sync.aligned.m16n8k8.row.col.f32.tf32.tf32.f32 "
        "{%0,%1,%2,%3}, {%4,%5,%6,%7}, {%8,%9}, {%10,%11,%12,%13};"
        : "=f"(c[0]), "=f"(c[1]), "=f"(c[2]), "=f"(c[3])
        : "r"(a[0]), "r"(a[1]), "r"(a[2]), "r"(a[3]),
          "r"(b[0]), "r"(b[1]),
          "f"(c[0]), "f"(c[1]), "f"(c[2]), "f"(c[3]));
}

__device__ __forceinline__ uint32_t smem_u32(const void* p) {
    uint32_t a;
    asm("{ .reg .u64 t; cvta.to.shared.u64 t, %1; cvt.u32.u64 %0, t; }" : "=r"(a) : "l"(p));
    return a;
}

#define CP_ASYNC16(dst, src) \
    asm volatile("cp.async.cg.shared.global [%0], [%1], 16;" :: "r"(dst), "l"(src))
#define CP_COMMIT() asm volatile("cp.async.commit_group;" ::: "memory")
#define CP_WAIT(n)  asm volatile("cp.async.wait_group %0;" :: "n"(n) : "memory")

// ------------------------------ tf32 GEMM ----------------------------------
#define APAD_STRIDE 36
#define BPAD_STRIDE 136
#define A_STAGE_FLOATS (128 * APAD_STRIDE)
#define B_STAGE_FLOATS (32 * BPAD_STRIDE)
#define STAGE_FLOATS   (A_STAGE_FLOATS + B_STAGE_FLOATS)
#define GEMM_SMEM_BYTES (2 * STAGE_FLOATS * 4)

template<bool RELU, bool RES, bool ROUND>
__global__ void __launch_bounds__(256, 2) mma_gemm_kernel(
    const float* __restrict__ A, const float* __restrict__ B,
    const float* __restrict__ bias, const float* __restrict__ res,
    float* __restrict__ C, int N, int K)
{
    extern __shared__ float smem[];
    const uint32_t sbase = smem_u32(smem);

    const int tid = threadIdx.x;
    const int wid = tid >> 5, lid = tid & 31;
    const int gID = lid >> 2, tg = lid & 3;
    const int warp_m = wid >> 2, warp_n = wid & 3;
    const int bx = blockIdx.x, by = blockIdx.y;
    const int KT = K >> 5;

    float acc[4][4][4];
    #pragma unroll
    for (int mt = 0; mt < 4; mt++)
        #pragma unroll
        for (int nt = 0; nt < 4; nt++)
            #pragma unroll
            for (int r = 0; r < 4; r++) acc[mt][nt][r] = 0.f;

    const float* Ag0 = A + (size_t)(by * 128) * K;
    const float* Bg0 = B + (size_t)(bx * 128);

    auto load_stage = [&](int s, int kt) {
        const uint32_t sA = sbase + (uint32_t)(s * STAGE_FLOATS) * 4u;
        const uint32_t sB = sA + A_STAGE_FLOATS * 4u;
        const float* Ag = Ag0 + kt * 32;
        const float* Bg = Bg0 + (size_t)(kt * 32) * N;
        #pragma unroll
        for (int i = 0; i < 4; i++) {
            const int idx = tid + i * 256;
            const int ar = idx >> 3, ac = (idx & 7) * 4;
            CP_ASYNC16(sA + (uint32_t)(ar * APAD_STRIDE + ac) * 4u,
                       Ag + (size_t)ar * K + ac);
            const int br = idx >> 5, bc = (idx & 31) * 4;
            CP_ASYNC16(sB + (uint32_t)(br * BPAD_STRIDE + bc) * 4u,
                       Bg + (size_t)br * N + bc);
        }
    };

    load_stage(0, 0);
    CP_COMMIT();

    for (int kt = 0; kt < KT; kt++) {
        if (kt + 1 < KT) {
            load_stage((kt + 1) & 1, kt + 1);
            CP_COMMIT();
            CP_WAIT(1);
        } else {
            CP_WAIT(0);
        }
        __syncthreads();

        const float* As_ = smem + (kt & 1) * STAGE_FLOATS;
        const float* Bs_ = As_ + A_STAGE_FLOATS;

        #pragma unroll
        for (int ks = 0; ks < 4; ks++) {
            const int kb = ks * 8;
            uint32_t afr[4][4];
            uint32_t bfr[4][2];
            #pragma unroll
            for (int mt = 0; mt < 4; mt++) {
                const float* ap = As_ + (warp_m * 64 + mt * 16 + gID) * APAD_STRIDE + kb + tg;
                afr[mt][0] = __float_as_uint(ap[0]);
                afr[mt][1] = __float_as_uint(ap[8 * APAD_STRIDE]);
                afr[mt][2] = __float_as_uint(ap[4]);
                afr[mt][3] = __float_as_uint(ap[8 * APAD_STRIDE + 4]);
            }
            #pragma unroll
            for (int nt = 0; nt < 4; nt++) {
                const float* bp = Bs_ + (kb + tg) * BPAD_STRIDE + warp_n * 32 + nt * 8 + gID;
                bfr[nt][0] = __float_as_uint(bp[0]);
                bfr[nt][1] = __float_as_uint(bp[4 * BPAD_STRIDE]);
            }
            #pragma unroll
            for (int mt = 0; mt < 4; mt++)
                #pragma unroll
                for (int nt = 0; nt < 4; nt++)
                    mma_tf32(acc[mt][nt], afr[mt], bfr[nt]);
        }
        __syncthreads();
    }

    const int row_base = by * 128 + warp_m * 64 + gID;
    const int col_base = bx * 128 + warp_n * 32 + 2 * tg;
    #pragma unroll
    for (int mt = 0; mt < 4; mt++) {
        const int r0 = row_base + mt * 16;
        const int r1 = r0 + 8;
        #pragma unroll
        for (int nt = 0; nt < 4; nt++) {
            const int c = col_base + nt * 8;
            const float2 bv = *(const float2*)(bias + c);
            float2 o0 = make_float2(acc[mt][nt][0] + bv.x, acc[mt][nt][1] + bv.y);
            float2 o1 = make_float2(acc[mt][nt][2] + bv.x, acc[mt][nt][3] + bv.y);
            if (RES) {
                const float2 q0 = *(const float2*)(res + (size_t)r0 * N + c);
                const float2 q1 = *(const float2*)(res + (size_t)r1 * N + c);
                o0.x += q0.x; o0.y += q0.y;
                o1.x += q1.x; o1.y += q1.y;
            }
            if (RELU) {
                o0.x = fmaxf(o0.x, 0.f); o0.y = fmaxf(o0.y, 0.f);
                o1.x = fmaxf(o1.x, 0.f); o1.y = fmaxf(o1.y, 0.f);
            }
            if (ROUND) {
                o0.x = to_tf32(o0.x); o0.y = to_tf32(o0.y);
                o1.x = to_tf32(o1.x); o1.y = to_tf32(o1.y);
            }
            *(float2*)(C + (size_t)r0 * N + c) = o0;
            *(float2*)(C + (size_t)r1 * N + c) = o1;
        }
    }
}

// --------------------------- weight pre-passes -----------------------------
__global__ __launch_bounds__(256) void pack_qkv_w_kernel(
    const float* __restrict__ wq, const float* __restrict__ wk,
    const float* __restrict__ wv, float* __restrict__ out)
{
    const int idx = blockIdx.x * 256 + threadIdx.x;
    if (idx >= DMODEL * 3 * DMODEL) return;
    const int k = idx / (3 * DMODEL);
    const int c = idx - k * (3 * DMODEL);
    const float* src = (c < DMODEL) ? wq : (c < 2 * DMODEL ? wk : wv);
    const int cc = c & (DMODEL - 1);
    out[idx] = to_tf32(src[k * DMODEL + cc]);
}

__global__ __launch_bounds__(256) void pack_bias_kernel(
    const float* __restrict__ bq, const float* __restrict__ bk,
    const float* __restrict__ bv, float* __restrict__ out)
{
    const int c = blockIdx.x * 256 + threadIdx.x;
    if (c >= 3 * DMODEL) return;
    const float* src = (c < DMODEL) ? bq : (c < 2 * DMODEL ? bk : bv);
    out[c] = src[c & (DMODEL - 1)];
}

__global__ __launch_bounds__(256) void round_copy4_kernel(
    const float* __restrict__ in, float* __restrict__ out, int n4)
{
    const int i = blockIdx.x * 256 + threadIdx.x;
    if (i >= n4) return;
    float4 v = ((const float4*)in)[i];
    v.x = to_tf32(v.x); v.y = to_tf32(v.y);
    v.z = to_tf32(v.z); v.w = to_tf32(v.w);
    ((float4*)out)[i] = v;
}

// ------------------------------- LayerNorm ---------------------------------
template<bool ROUND>
__global__ __launch_bounds__(256) void ln_kernel(
    const float* __restrict__ X, const float* __restrict__ gamma,
    const float* __restrict__ beta, float* __restrict__ Y)
{
    __shared__ float red[8];
    __shared__ float sh_mu, sh_rstd;
    const int row = blockIdx.x;
    const int tid = threadIdx.x;

    const float4* xr = (const float4*)(X + (size_t)row * DMODEL);
    float4 v = xr[tid];

    float s = v.x + v.y + v.z + v.w;
    #pragma unroll
    for (int o = 16; o; o >>= 1) s += __shfl_xor_sync(0xffffffffu, s, o);
    if ((tid & 31) == 0) red[tid >> 5] = s;
    __syncthreads();
    if (tid == 0) {
        float t = 0.f;
        #pragma unroll
        for (int i = 0; i < 8; i++) t += red[i];
        sh_mu = t * (1.0f / DMODEL);
    }
    __syncthreads();
    const float mu = sh_mu;

    float4 d = make_float4(v.x - mu, v.y - mu, v.z - mu, v.w - mu);
    float sq = d.x*d.x + d.y*d.y + d.z*d.z + d.w*d.w;
    #pragma unroll
    for (int o = 16; o; o >>= 1) sq += __shfl_xor_sync(0xffffffffu, sq, o);
    __syncthreads();
    if ((tid & 31) == 0) red[tid >> 5] = sq;
    __syncthreads();
    if (tid == 0) {
        float t = 0.f;
        #pragma unroll
        for (int i = 0; i < 8; i++) t += red[i];
        sh_rstd = rsqrtf(t * (1.0f / DMODEL) + LN_EPS);
    }
    __syncthreads();
    const float rstd = sh_rstd;

    float4 gv = ((const float4*)gamma)[tid];
    float4 bv = ((const float4*)beta)[tid];
    float4 o;
    o.x = d.x * rstd * gv.x + bv.x;
    o.y = d.y * rstd * gv.y + bv.y;
    o.z = d.z * rstd * gv.z + bv.z;
    o.w = d.w * rstd * gv.w + bv.w;
    if (ROUND) {
        o.x = to_tf32(o.x); o.y = to_tf32(o.y);
        o.z = to_tf32(o.z); o.w = to_tf32(o.w);
    }
    ((float4*)(Y + (size_t)row * DMODEL))[tid] = o;
}

// ---------------------- mma tf32 flash attention ---------------------------
// QKV fused layout: row stride 3*DMODEL; q@+0, k@+DMODEL, v@+2*DMODEL.
// CTA: 256 thr (8 warps), 128 queries; key tiles of 64, double-buffered cp.async.
// Per warp: 16 query rows; S=Q·K^T via mma, online softmax in C-frag layout,
// P staged through warp-private smem (re-layout to A-frags), O += P·V via mma.
#define QKV_LD   (3 * DMODEL)
#define ATT_BM   128
#define ATT_BN   64
#define KPAD     68
#define VPAD     72
#define PPAD     68
#define ATT_K_FLOATS (2 * ATT_BN * KPAD)     // 8704
#define ATT_V_FLOATS (2 * ATT_BN * VPAD)     // 9216
#define ATT_P_FLOATS (ATT_BM * PPAD)         // 8704
#define ATT_SMEM_BYTES ((ATT_K_FLOATS + ATT_V_FLOATS + ATT_P_FLOATS) * 4)  // 106496

__global__ void __launch_bounds__(256, 2) mma_attn_kernel(
    const float* __restrict__ QKV, float* __restrict__ O)
{
    extern __shared__ float sm[];
    float* Ksm = sm;
    float* Vsm = sm + ATT_K_FLOATS;
    float* Psm = Vsm + ATT_V_FLOATS;

    const int tid = threadIdx.x;
    const int wid = tid >> 5, lid = tid & 31;
    const int gID = lid >> 2, tg = lid & 3;
    const int b = blockIdx.z, h = blockIdx.y;
    const int q0 = blockIdx.x * ATT_BM;
    const int wrow = wid * 16;

    const float* Qb = QKV + (size_t)(b * SEQ + q0 + wrow) * QKV_LD + h * DHEAD;
    const float* Kb = QKV + (size_t)(b * SEQ) * QKV_LD + DMODEL + h * DHEAD;
    const float* Vb = Kb + DMODEL;

    // preload Q a-frags (scale * log2e folded, tf32-rounded)
    const float qscale = 0.125f * 1.4426950408889634f;
    float qa[8][4];
    #pragma unroll
    for (int ks = 0; ks < 8; ks++) {
        const int d0 = ks * 8 + tg;
        qa[ks][0] = to_tf32(Qb[(size_t)gID * QKV_LD + d0] * qscale);
        qa[ks][1] = to_tf32(Qb[(size_t)(gID + 8) * QKV_LD + d0] * qscale);
        qa[ks][2] = to_tf32(Qb[(size_t)gID * QKV_LD + d0 + 4] * qscale);
        qa[ks][3] = to_tf32(Qb[(size_t)(gID + 8) * QKV_LD + d0 + 4] * qscale);
    }

    float o[8][4];
    #pragma unroll
    for (int nt = 0; nt < 8; nt++)
        #pragma unroll
        for (int r = 0; r < 4; r++) o[nt][r] = 0.f;
    float m0 = -1e30f, m1 = -1e30f, l0 = 0.f, l1 = 0.f;

    const uint32_t kbase = smem_u32(Ksm);
    const uint32_t vbase = smem_u32(Vsm);

    auto load_kv = [&](int jt) {
        const int s = jt & 1;
        const float* Kg = Kb + (size_t)(jt * ATT_BN) * QKV_LD;
        const float* Vg = Vb + (size_t)(jt * ATT_BN) * QKV_LD;
        const uint32_t kdst = kbase + (uint32_t)(s * ATT_BN * KPAD) * 4u;
        const uint32_t vdst = vbase + (uint32_t)(s * ATT_BN * VPAD) * 4u;
        #pragma unroll
        for (int i = 0; i < 4; i++) {
            const int c = tid + i * 256;          // 0..1023
            const int r = c >> 4, col = (c & 15) * 4;
            CP_ASYNC16(kdst + (uint32_t)(r * KPAD + col) * 4u,
                       Kg + (size_t)r * QKV_LD + col);
            CP_ASYNC16(vdst + (uint32_t)(r * VPAD + col) * 4u,
                       Vg + (size_t)r * QKV_LD + col);
        }
    };

    load_kv(0);
    CP_COMMIT();

    const int NT = SEQ / ATT_BN;   // 16
    float* Pw = Psm + wrow * PPAD;

    for (int jt = 0; jt < NT; jt++) {
        CP_WAIT(0);
        __syncthreads();
        if (jt + 1 < NT) { load_kv(jt + 1); CP_COMMIT(); }

        const float* Kt = Ksm + (jt & 1) * ATT_BN * KPAD;
        const float* Vt = Vsm + (jt & 1) * ATT_BN * VPAD;

        // S = Q K^T (log2 domain)
        float s[8][4];
        #pragma unroll
        for (int nt = 0; nt < 8; nt++)
            #pragma unroll
            for (int r = 0; r < 4; r++) s[nt][r] = 0.f;

        #pragma unroll
        for (int ks = 0; ks < 8; ks++) {
            const int d0 = ks * 8 + tg;
            #pragma unroll
            for (int nt = 0; nt < 8; nt++) {
                const float* kp = Kt + (nt * 8 + gID) * KPAD + d0;
                uint32_t bfr[2] = { __float_as_uint(kp[0]), __float_as_uint(kp[4]) };
                mma_tf32(s[nt], reinterpret_cast<const uint32_t*>(qa[ks]), bfr);
            }
        }

        // online softmax (rows gID / gID+8)
        float mx0 = s[0][0], mx1 = s[0][2];
        #pragma unroll
        for (int nt = 0; nt < 8; nt++) {
            mx0 = fmaxf(mx0, fmaxf(s[nt][0], s[nt][1]));
            mx1 = fmaxf(mx1, fmaxf(s[nt][2], s[nt][3]));
        }
        mx0 = fmaxf(mx0, __shfl_xor_sync(0xffffffffu, mx0, 1));
        mx0 = fmaxf(mx0, __shfl_xor_sync(0xffffffffu, mx0, 2));
        mx1 = fmaxf(mx1, __shfl_xor_sync(0xffffffffu, mx1, 1));
        mx1 = fmaxf(mx1, __shfl_xor_sync(0xffffffffu, mx1, 2));

        const float mn0 = fmaxf(m0, mx0), mn1 = fmaxf(m1, mx1);
        const float a0 = exp2f(m0 - mn0), a1 = exp2f(m1 - mn1);
        m0 = mn0; m1 = mn1;

        float ls0 = 0.f, ls1 = 0.f;
        #pragma unroll
        for (int nt = 0; nt < 8; nt++) {
            const float p0 = exp2f(s[nt][0] - m0);
            const float p1 = exp2f(s[nt][1] - m0);
            const float p2 = exp2f(s[nt][2] - m1);
            const float p3 = exp2f(s[nt][3] - m1);
            ls0 += p0 + p1;
            ls1 += p2 + p3;
            float2* pr0 = (float2*)(Pw + gID * PPAD + nt * 8 + 2 * tg);
            float2* pr1 = (float2*)(Pw + (gID + 8) * PPAD + nt * 8 + 2 * tg);
            *pr0 = make_float2(to_tf32(p0), to_tf32(p1));
            *pr1 = make_float2(to_tf32(p2), to_tf32(p3));
            o[nt][0] *= a0; o[nt][1] *= a0;
            o[nt][2] *= a1; o[nt][3] *= a1;
        }
        l0 = l0 * a0 + ls0;
        l1 = l1 * a1 + ls1;
        __syncwarp();

        // O += P V
        #pragma unroll
        for (int ks = 0; ks < 8; ks++) {
            const int k0 = ks * 8 + tg;
            uint32_t pa[4];
            pa[0] = __float_as_uint(Pw[gID * PPAD + k0]);
            pa[1] = __float_as_uint(Pw[(gID + 8) * PPAD + k0]);
            pa[2] = __float_as_uint(Pw[gID * PPAD + k0 + 4]);
            pa[3] = __float_as_uint(Pw[(gID + 8) * PPAD + k0 + 4]);
            #pragma unroll
            for (int nt = 0; nt < 8; nt++) {
                const float* vp = Vt + k0 * VPAD + nt * 8 + gID;
                uint32_t bfr[2] = { __float_as_uint(vp[0]), __float_as_uint(vp[4 * VPAD]) };
                mma_tf32(o[nt], pa, bfr);
            }
        }
        __syncwarp();   // P reuse next iter (same warp; ordering hygiene)
    }

    // finalize
    l0 += __shfl_xor_sync(0xffffffffu, l0, 1);
    l0 += __shfl_xor_sync(0xffffffffu, l0, 2);
    l1 += __shfl_xor_sync(0xffffffffu, l1, 1);
    l1 += __shfl_xor_sync(0xffffffffu, l1, 2);
    const float inv0 = 1.0f / l0, inv1 = 1.0f / l1;

    const int r0 = b * SEQ + q0 + wrow + gID;
    const int r1 = r0 + 8;
    float* O0 = O + (size_t)r0 * DMODEL + h * DHEAD + 2 * tg;
    float* O1 = O + (size_t)r1 * DMODEL + h * DHEAD + 2 * tg;
    #pragma unroll
    for (int nt = 0; nt < 8; nt++) {
        *(float2*)(O0 + nt * 8) = make_float2(to_tf32(o[nt][0] * inv0), to_tf32(o[nt][1] * inv0));
        *(float2*)(O1 + nt * 8) = make_float2(to_tf32(o[nt][2] * inv1), to_tf32(o[nt][3] * inv1));
    }
}

// ------------------------------- launcher ----------------------------------
extern "C" void kernel_launch(void* const* d_in, const int* in_sizes, int n_in,
                              void* d_out, int out_size)
{
    const float* src   = (const float*)d_in[0];
    const float* Wq    = (const float*)d_in[1];
    const float* bq    = (const float*)d_in[2];
    const float* Wk    = (const float*)d_in[3];
    const float* bk    = (const float*)d_in[4];
    const float* Wv    = (const float*)d_in[5];
    const float* bv    = (const float*)d_in[6];
    const float* Wo    = (const float*)d_in[7];
    const float* bo    = (const float*)d_in[8];
    const float* W1    = (const float*)d_in[9];
    const float* b1    = (const float*)d_in[10];
    const float* W2    = (const float*)d_in[11];
    const float* b2    = (const float*)d_in[12];
    const float* g1    = (const float*)d_in[13];
    const float* beta1 = (const float*)d_in[14];
    const float* g2    = (const float*)d_in[15];
    const float* beta2 = (const float*)d_in[16];
    float* out = (float*)d_out;

    float *x, *qkv, *ctx, *y, *hbuf, *wqkv, *bqkv, *wor, *w1r, *w2r;
    cudaGetSymbolAddress((void**)&x,    g_x);
    cudaGetSymbolAddress((void**)&qkv,  g_qkv);
    cudaGetSymbolAddress((void**)&ctx,  g_ctx);
    cudaGetSymbolAddress((void**)&y,    g_y);
    cudaGetSymbolAddress((void**)&hbuf, g_h);
    cudaGetSymbolAddress((void**)&wqkv, g_wqkv);
    cudaGetSymbolAddress((void**)&bqkv, g_bqkv);
    cudaGetSymbolAddress((void**)&wor,  g_wor);
    cudaGetSymbolAddress((void**)&w1r,  g_w1r);
    cudaGetSymbolAddress((void**)&w2r,  g_w2r);

    cudaFuncSetAttribute(mma_gemm_kernel<false,false,false>,
        cudaFuncAttributeMaxDynamicSharedMemorySize, GEMM_SMEM_BYTES);
    cudaFuncSetAttribute(mma_gemm_kernel<false,true,false>,
        cudaFuncAttributeMaxDynamicSharedMemorySize, GEMM_SMEM_BYTES);
    cudaFuncSetAttribute(mma_gemm_kernel<true,false,true>,
        cudaFuncAttributeMaxDynamicSharedMemorySize, GEMM_SMEM_BYTES);
    cudaFuncSetAttribute(mma_attn_kernel,
        cudaFuncAttributeMaxDynamicSharedMemorySize, ATT_SMEM_BYTES);

    // 0) weight/bias pre-passes (round to tf32; pack QKV)
    pack_qkv_w_kernel<<<(DMODEL * 3 * DMODEL + 255) / 256, 256>>>(Wq, Wk, Wv, wqkv);
    pack_bias_kernel<<<(3 * DMODEL + 255) / 256, 256>>>(bq, bk, bv, bqkv);
    round_copy4_kernel<<<(DMODEL * DMODEL / 4 + 255) / 256, 256>>>(Wo, wor, DMODEL * DMODEL / 4);
    round_copy4_kernel<<<(DMODEL * DFF / 4 + 255) / 256, 256>>>(W1, w1r, DMODEL * DFF / 4);
    round_copy4_kernel<<<(DFF * DMODEL / 4 + 255) / 256, 256>>>(W2, w2r, DFF * DMODEL / 4);

    // 1) LN1 (tf32-rounded output)
    ln_kernel<true><<<NTOK, 256>>>(src, g1, beta1, x);

    // 2) fused QKV projection: [8192,1024] @ [1024,3072]
    {
        dim3 g(3 * DMODEL / 128, NTOK / 128);
        mma_gemm_kernel<false,false,false><<<g, 256, GEMM_SMEM_BYTES>>>(
            x, wqkv, bqkv, nullptr, qkv, 3 * DMODEL, DMODEL);
    }

    // 3) attention (tensor-core flash; ctx tf32-rounded)
    {
        dim3 g(SEQ / ATT_BM, NHEAD, BATCH);   // (8,16,8)
        mma_attn_kernel<<<g, 256, ATT_SMEM_BYTES>>>(qkv, ctx);
    }

    // 4) output projection + residual -> d_out
    {
        dim3 g(DMODEL / 128, NTOK / 128);
        mma_gemm_kernel<false,true,false><<<g, 256, GEMM_SMEM_BYTES>>>(
            ctx, wor, bo, src, out, DMODEL, DMODEL);
    }

    // 5) LN2 (tf32-rounded output)
    ln_kernel<true><<<NTOK, 256>>>(out, g2, beta2, y);

    // 6) FFN up + ReLU (rounded store)
    {
        dim3 g(DFF / 128, NTOK / 128);
        mma_gemm_kernel<true,false,true><<<g, 256, GEMM_SMEM_BYTES>>>(
            y, w1r, b1, nullptr, hbuf, DFF, DMODEL);
    }

    // 7) FFN down + bias + residual (in-place on d_out)
    {
        dim3 g(DMODEL / 128, NTOK / 128);
        mma_gemm_kernel<false,true,false><<<g, 256, GEMM_SMEM_BYTES>>>(
            hbuf, w2r, b2, out, out, DMODEL, DFF);
    }
}

// round 11
// speedup vs baseline: 5.7786x; 1.4192x over previous
#include <cuda_runtime.h>
#include <cuda_bf16.h>
#include <math.h>
#include <stdint.h>

// ---------------------------------------------------------------------------
// CustomEncoderLayer on GB300 (sm_103 PTX target — no 'a' features).
// R10: linear GEMMs via bf16 mma.sync m16n8k16 (fp32 accum); attention stays
// tf32 mma flash. Activations bf16 between GEMMs; residuals fp32.
// ---------------------------------------------------------------------------

#define BATCH   8
#define SEQ     1024
#define DMODEL  1024
#define NHEAD   16
#define DHEAD   64
#define DFF     4096
#define NTOK    (BATCH * SEQ)          // 8192
#define LN_EPS  1e-5f

typedef __nv_bfloat16  bf16;
typedef __nv_bfloat162 bf162;

// ------------------------- scratch (static device) -------------------------
__device__ bf16  g_x    [NTOK * DMODEL];        // LN1 out (bf16)
__device__ float g_qkv  [NTOK * 3 * DMODEL];    // fused q|k|v (fp32, attn input)
__device__ bf16  g_ctx  [NTOK * DMODEL];        // attention out (bf16)
__device__ bf16  g_y    [NTOK * DMODEL];        // LN2 out (bf16)
__device__ bf16  g_h    [NTOK * DFF];           // FFN hidden (bf16)
__device__ bf16  g_wqkvT[3 * DMODEL * DMODEL];  // [3N, K] bf16
__device__ float g_bqkv [3 * DMODEL];
__device__ bf16  g_woT  [DMODEL * DMODEL];      // [N, K]
__device__ bf16  g_w1T  [DFF * DMODEL];
__device__ bf16  g_w2T  [DMODEL * DFF];

// ------------------------------ helpers ------------------------------------
__device__ __forceinline__ float to_tf32(float x) {
    float r;
    asm("cvt.rna.tf32.f32 %0, %1;" : "=f"(r) : "f"(x));
    return r;
}

__device__ __forceinline__ void mma_tf32(float c[4], const uint32_t a[4], const uint32_t b[2]) {
    asm volatile(
        "mma.sync.aligned.m16n8k8.row.col.f32.tf32.tf32.f32 "
        "{%0,%1,%2,%3}, {%4,%5,%6,%7}, {%8,%9}, {%10,%11,%12,%13};"
        : "=f"(c[0]), "=f"(c[1]), "=f"(c[2]), "=f"(c[3])
        : "r"(a[0]), "r"(a[1]), "r"(a[2]), "r"(a[3]),
          "r"(b[0]), "r"(b[1]),
          "f"(c[0]), "f"(c[1]), "f"(c[2]), "f"(c[3]));
}

__device__ __forceinline__ void mma_bf16(float c[4], const uint32_t a[4], const uint32_t b[2]) {
    asm volatile(
        "mma.sync.aligned.m16n8k16.row.col.f32.bf16.bf16.f32 "
        "{%0,%1,%2,%3}, {%4,%5,%6,%7}, {%8,%9}, {%10,%11,%12,%13};"
        : "=f"(c[0]), "=f"(c[1]), "=f"(c[2]), "=f"(c[3])
        : "r"(a[0]), "r"(a[1]), "r"(a[2]), "r"(a[3]),
          "r"(b[0]), "r"(b[1]),
          "f"(c[0]), "f"(c[1]), "f"(c[2]), "f"(c[3]));
}

__device__ __forceinline__ uint32_t smem_u32(const void* p) {
    uint32_t a;
    asm("{ .reg .u64 t; cvta.to.shared.u64 t, %1; cvt.u32.u64 %0, t; }" : "=r"(a) : "l"(p));
    return a;
}

#define CP_ASYNC16(dst, src) \
    asm volatile("cp.async.cg.shared.global [%0], [%1], 16;" :: "r"(dst), "l"(src))
#define CP_COMMIT() asm volatile("cp.async.commit_group;" ::: "memory")
#define CP_WAIT(n)  asm volatile("cp.async.wait_group %0;" :: "n"(n) : "memory")

// ------------------------------ bf16 GEMM ----------------------------------
// C[M,N] = A[M,K] @ BT[N,K]^T + bias (+res) (relu).  A,BT bf16 K-contiguous.
// BM=BN=128, BK=32, 256 thr, 8 warps (2m x 4n), warp tile 64x32,
// double-buffered cp.async. fp32 accumulate. OUTBF: store bf16, else fp32.
#define GPAD 40                               // bf16 units per smem row
#define G_TILE_ELEMS (128 * GPAD)             // 5120 bf16 per operand tile
#define G_STAGE_ELEMS (2 * G_TILE_ELEMS)      // A + B
#define GEMM_SMEM_BYTES (2 * G_STAGE_ELEMS * 2)  // 40960

template<bool RELU, bool RES, bool OUTBF>
__global__ void __launch_bounds__(256, 2) bf16_gemm_kernel(
    const bf16* __restrict__ A, const bf16* __restrict__ BT,
    const float* __restrict__ bias, const float* __restrict__ res,
    void* __restrict__ Cv, int N, int K)
{
    extern __shared__ bf16 smem[];
    const uint32_t sbase = smem_u32(smem);

    const int tid = threadIdx.x;
    const int wid = tid >> 5, lid = tid & 31;
    const int gID = lid >> 2, tg = lid & 3;
    const int warp_m = wid >> 2, warp_n = wid & 3;
    const int bx = blockIdx.x, by = blockIdx.y;
    const int KT = K >> 5;

    float acc[4][4][4];
    #pragma unroll
    for (int mt = 0; mt < 4; mt++)
        #pragma unroll
        for (int nt = 0; nt < 4; nt++)
            #pragma unroll
            for (int r = 0; r < 4; r++) acc[mt][nt][r] = 0.f;

    const bf16* Ag0 = A  + (size_t)(by * 128) * K;
    const bf16* Bg0 = BT + (size_t)(bx * 128) * K;

    auto load_stage = [&](int s, int kt) {
        const uint32_t sA = sbase + (uint32_t)(s * G_STAGE_ELEMS) * 2u;
        const uint32_t sB = sA + G_TILE_ELEMS * 2u;
        const bf16* Ag = Ag0 + kt * 32;
        const bf16* Bg = Bg0 + kt * 32;
        #pragma unroll
        for (int i = 0; i < 2; i++) {
            const int idx = tid + i * 256;        // 0..511
            const int r = idx >> 2, c = (idx & 3) * 8;
            CP_ASYNC16(sA + (uint32_t)(r * GPAD + c) * 2u, Ag + (size_t)r * K + c);
            CP_ASYNC16(sB + (uint32_t)(r * GPAD + c) * 2u, Bg + (size_t)r * K + c);
        }
    };

    load_stage(0, 0);
    CP_COMMIT();

    for (int kt = 0; kt < KT; kt++) {
        if (kt + 1 < KT) {
            load_stage((kt + 1) & 1, kt + 1);
            CP_COMMIT();
            CP_WAIT(1);
        } else {
            CP_WAIT(0);
        }
        __syncthreads();

        const bf16* As_ = smem + (kt & 1) * G_STAGE_ELEMS;
        const bf16* Bs_ = As_ + G_TILE_ELEMS;

        #pragma unroll
        for (int ks = 0; ks < 2; ks++) {
            const int kb = ks * 16 + 2 * tg;
            uint32_t afr[4][4];
            uint32_t bfr[4][2];
            #pragma unroll
            for (int mt = 0; mt < 4; mt++) {
                const bf16* ap = As_ + (warp_m * 64 + mt * 16 + gID) * GPAD + kb;
                afr[mt][0] = *(const uint32_t*)ap;
                afr[mt][1] = *(const uint32_t*)(ap + 8 * GPAD);
                afr[mt][2] = *(const uint32_t*)(ap + 8);
                afr[mt][3] = *(const uint32_t*)(ap + 8 * GPAD + 8);
            }
            #pragma unroll
            for (int nt = 0; nt < 4; nt++) {
                const bf16* bp = Bs_ + (warp_n * 32 + nt * 8 + gID) * GPAD + kb;
                bfr[nt][0] = *(const uint32_t*)bp;
                bfr[nt][1] = *(const uint32_t*)(bp + 8);
            }
            #pragma unroll
            for (int mt = 0; mt < 4; mt++)
                #pragma unroll
                for (int nt = 0; nt < 4; nt++)
                    mma_bf16(acc[mt][nt], afr[mt], bfr[nt]);
        }
        __syncthreads();
    }

    // epilogue
    const int row_base = by * 128 + warp_m * 64 + gID;
    const int col_base = bx * 128 + warp_n * 32 + 2 * tg;
    #pragma unroll
    for (int mt = 0; mt < 4; mt++) {
        const int r0 = row_base + mt * 16;
        const int r1 = r0 + 8;
        #pragma unroll
        for (int nt = 0; nt < 4; nt++) {
            const int c = col_base + nt * 8;
            const float2 bv = *(const float2*)(bias + c);
            float2 o0 = make_float2(acc[mt][nt][0] + bv.x, acc[mt][nt][1] + bv.y);
            float2 o1 = make_float2(acc[mt][nt][2] + bv.x, acc[mt][nt][3] + bv.y);
            if (RES) {
                const float2 q0 = *(const float2*)(res + (size_t)r0 * N + c);
                const float2 q1 = *(const float2*)(res + (size_t)r1 * N + c);
                o0.x += q0.x; o0.y += q0.y;
                o1.x += q1.x; o1.y += q1.y;
            }
            if (RELU) {
                o0.x = fmaxf(o0.x, 0.f); o0.y = fmaxf(o0.y, 0.f);
                o1.x = fmaxf(o1.x, 0.f); o1.y = fmaxf(o1.y, 0.f);
            }
            if (OUTBF) {
                bf16* C = (bf16*)Cv;
                *(bf162*)(C + (size_t)r0 * N + c) = __floats2bfloat162_rn(o0.x, o0.y);
                *(bf162*)(C + (size_t)r1 * N + c) = __floats2bfloat162_rn(o1.x, o1.y);
            } else {
                float* C = (float*)Cv;
                *(float2*)(C + (size_t)r0 * N + c) = o0;
                *(float2*)(C + (size_t)r1 * N + c) = o1;
            }
        }
    }
}

// --------------------------- weight pre-passes -----------------------------
// fp32 [R][C] -> bf16 [C][R]
__global__ __launch_bounds__(256) void transpose_bf16_kernel(
    const float* __restrict__ in, bf16* __restrict__ out, int R, int C)
{
    __shared__ float t[32][33];
    const int bx = blockIdx.x * 32, by = blockIdx.y * 32;
    const int tx = threadIdx.x & 31, ty = threadIdx.x >> 5;   // 32x8
    #pragma unroll
    for (int i = 0; i < 32; i += 8)
        t[ty + i][tx] = in[(size_t)(by + ty + i) * C + bx + tx];
    __syncthreads();
    #pragma unroll
    for (int i = 0; i < 32; i += 8)
        out[(size_t)(bx + ty + i) * R + by + tx] = __float2bfloat16(t[tx][ty + i]);
}

__global__ __launch_bounds__(256) void pack_bias_kernel(
    const float* __restrict__ bq, const float* __restrict__ bk,
    const float* __restrict__ bv, float* __restrict__ out)
{
    const int c = blockIdx.x * 256 + threadIdx.x;
    if (c >= 3 * DMODEL) return;
    const float* src = (c < DMODEL) ? bq : (c < 2 * DMODEL ? bk : bv);
    out[c] = src[c & (DMODEL - 1)];
}

// ------------------------------- LayerNorm ---------------------------------
// input fp32; output bf16
__global__ __launch_bounds__(256) void ln_kernel(
    const float* __restrict__ X, const float* __restrict__ gamma,
    const float* __restrict__ beta, bf16* __restrict__ Y)
{
    __shared__ float red[8];
    __shared__ float sh_mu, sh_rstd;
    const int row = blockIdx.x;
    const int tid = threadIdx.x;

    const float4* xr = (const float4*)(X + (size_t)row * DMODEL);
    float4 v = xr[tid];

    float s = v.x + v.y + v.z + v.w;
    #pragma unroll
    for (int o = 16; o; o >>= 1) s += __shfl_xor_sync(0xffffffffu, s, o);
    if ((tid & 31) == 0) red[tid >> 5] = s;
    __syncthreads();
    if (tid == 0) {
        float t = 0.f;
        #pragma unroll
        for (int i = 0; i < 8; i++) t += red[i];
        sh_mu = t * (1.0f / DMODEL);
    }
    __syncthreads();
    const float mu = sh_mu;

    float4 d = make_float4(v.x - mu, v.y - mu, v.z - mu, v.w - mu);
    float sq = d.x*d.x + d.y*d.y + d.z*d.z + d.w*d.w;
    #pragma unroll
    for (int o = 16; o; o >>= 1) sq += __shfl_xor_sync(0xffffffffu, sq, o);
    __syncthreads();
    if ((tid & 31) == 0) red[tid >> 5] = sq;
    __syncthreads();
    if (tid == 0) {
        float t = 0.f;
        #pragma unroll
        for (int i = 0; i < 8; i++) t += red[i];
        sh_rstd = rsqrtf(t * (1.0f / DMODEL) + LN_EPS);
    }
    __syncthreads();
    const float rstd = sh_rstd;

    float4 gv = ((const float4*)gamma)[tid];
    float4 bv = ((const float4*)beta)[tid];
    float4 o;
    o.x = d.x * rstd * gv.x + bv.x;
    o.y = d.y * rstd * gv.y + bv.y;
    o.z = d.z * rstd * gv.z + bv.z;
    o.w = d.w * rstd * gv.w + bv.w;
    bf162* yr = (bf162*)(Y + (size_t)row * DMODEL);
    yr[2 * tid + 0] = __floats2bfloat162_rn(o.x, o.y);
    yr[2 * tid + 1] = __floats2bfloat162_rn(o.z, o.w);
}

// ---------------------- mma tf32 flash attention ---------------------------
// QKV fused layout fp32: row stride 3*DMODEL; q@+0, k@+DMODEL, v@+2*DMODEL.
// Output ctx: bf16.
#define QKV_LD   (3 * DMODEL)
#define ATT_BM   128
#define ATT_BN   64
#define KPAD     68
#define VPAD     72
#define PPAD     68
#define ATT_K_FLOATS (2 * ATT_BN * KPAD)
#define ATT_V_FLOATS (2 * ATT_BN * VPAD)
#define ATT_P_FLOATS (ATT_BM * PPAD)
#define ATT_SMEM_BYTES ((ATT_K_FLOATS + ATT_V_FLOATS + ATT_P_FLOATS) * 4)

__global__ void __launch_bounds__(256, 2) mma_attn_kernel(
    const float* __restrict__ QKV, bf16* __restrict__ O)
{
    extern __shared__ float sm[];
    float* Ksm = sm;
    float* Vsm = sm + ATT_K_FLOATS;
    float* Psm = Vsm + ATT_V_FLOATS;

    const int tid = threadIdx.x;
    const int wid = tid >> 5, lid = tid & 31;
    const int gID = lid >> 2, tg = lid & 3;
    const int b = blockIdx.z, h = blockIdx.y;
    const int q0 = blockIdx.x * ATT_BM;
    const int wrow = wid * 16;

    const float* Qb = QKV + (size_t)(b * SEQ + q0 + wrow) * QKV_LD + h * DHEAD;
    const float* Kb = QKV + (size_t)(b * SEQ) * QKV_LD + DMODEL + h * DHEAD;
    const float* Vb = Kb + DMODEL;

    const float qscale = 0.125f * 1.4426950408889634f;
    float qa[8][4];
    #pragma unroll
    for (int ks = 0; ks < 8; ks++) {
        const int d0 = ks * 8 + tg;
        qa[ks][0] = to_tf32(Qb[(size_t)gID * QKV_LD + d0] * qscale);
        qa[ks][1] = to_tf32(Qb[(size_t)(gID + 8) * QKV_LD + d0] * qscale);
        qa[ks][2] = to_tf32(Qb[(size_t)gID * QKV_LD + d0 + 4] * qscale);
        qa[ks][3] = to_tf32(Qb[(size_t)(gID + 8) * QKV_LD + d0 + 4] * qscale);
    }

    float o[8][4];
    #pragma unroll
    for (int nt = 0; nt < 8; nt++)
        #pragma unroll
        for (int r = 0; r < 4; r++) o[nt][r] = 0.f;
    float m0 = -1e30f, m1 = -1e30f, l0 = 0.f, l1 = 0.f;

    const uint32_t kbase = smem_u32(Ksm);
    const uint32_t vbase = smem_u32(Vsm);

    auto load_kv = [&](int jt) {
        const int s = jt & 1;
        const float* Kg = Kb + (size_t)(jt * ATT_BN) * QKV_LD;
        const float* Vg = Vb + (size_t)(jt * ATT_BN) * QKV_LD;
        const uint32_t kdst = kbase + (uint32_t)(s * ATT_BN * KPAD) * 4u;
        const uint32_t vdst = vbase + (uint32_t)(s * ATT_BN * VPAD) * 4u;
        #pragma unroll
        for (int i = 0; i < 4; i++) {
            const int c = tid + i * 256;
            const int r = c >> 4, col = (c & 15) * 4;
            CP_ASYNC16(kdst + (uint32_t)(r * KPAD + col) * 4u,
                       Kg + (size_t)r * QKV_LD + col);
            CP_ASYNC16(vdst + (uint32_t)(r * VPAD + col) * 4u,
                       Vg + (size_t)r * QKV_LD + col);
        }
    };

    load_kv(0);
    CP_COMMIT();

    const int NT = SEQ / ATT_BN;
    float* Pw = Psm + wrow * PPAD;

    for (int jt = 0; jt < NT; jt++) {
        CP_WAIT(0);
        __syncthreads();
        if (jt + 1 < NT) { load_kv(jt + 1); CP_COMMIT(); }

        const float* Kt = Ksm + (jt & 1) * ATT_BN * KPAD;
        const float* Vt = Vsm + (jt & 1) * ATT_BN * VPAD;

        float s[8][4];
        #pragma unroll
        for (int nt = 0; nt < 8; nt++)
            #pragma unroll
            for (int r = 0; r < 4; r++) s[nt][r] = 0.f;

        #pragma unroll
        for (int ks = 0; ks < 8; ks++) {
            const int d0 = ks * 8 + tg;
            #pragma unroll
            for (int nt = 0; nt < 8; nt++) {
                const float* kp = Kt + (nt * 8 + gID) * KPAD + d0;
                uint32_t bfr[2] = { __float_as_uint(kp[0]), __float_as_uint(kp[4]) };
                mma_tf32(s[nt], reinterpret_cast<const uint32_t*>(qa[ks]), bfr);
            }
        }

        float mx0 = s[0][0], mx1 = s[0][2];
        #pragma unroll
        for (int nt = 0; nt < 8; nt++) {
            mx0 = fmaxf(mx0, fmaxf(s[nt][0], s[nt][1]));
            mx1 = fmaxf(mx1, fmaxf(s[nt][2], s[nt][3]));
        }
        mx0 = fmaxf(mx0, __shfl_xor_sync(0xffffffffu, mx0, 1));
        mx0 = fmaxf(mx0, __shfl_xor_sync(0xffffffffu, mx0, 2));
        mx1 = fmaxf(mx1, __shfl_xor_sync(0xffffffffu, mx1, 1));
        mx1 = fmaxf(mx1, __shfl_xor_sync(0xffffffffu, mx1, 2));

        const float mn0 = fmaxf(m0, mx0), mn1 = fmaxf(m1, mx1);
        const float a0 = exp2f(m0 - mn0), a1 = exp2f(m1 - mn1);
        m0 = mn0; m1 = mn1;

        float ls0 = 0.f, ls1 = 0.f;
        #pragma unroll
        for (int nt = 0; nt < 8; nt++) {
            const float p0 = exp2f(s[nt][0] - m0);
            const float p1 = exp2f(s[nt][1] - m0);
            const float p2 = exp2f(s[nt][2] - m1);
            const float p3 = exp2f(s[nt][3] - m1);
            ls0 += p0 + p1;
            ls1 += p2 + p3;
            float2* pr0 = (float2*)(Pw + gID * PPAD + nt * 8 + 2 * tg);
            float2* pr1 = (float2*)(Pw + (gID + 8) * PPAD + nt * 8 + 2 * tg);
            *pr0 = make_float2(to_tf32(p0), to_tf32(p1));
            *pr1 = make_float2(to_tf32(p2), to_tf32(p3));
            o[nt][0] *= a0; o[nt][1] *= a0;
            o[nt][2] *= a1; o[nt][3] *= a1;
        }
        l0 = l0 * a0 + ls0;
        l1 = l1 * a1 + ls1;
        __syncwarp();

        #pragma unroll
        for (int ks = 0; ks < 8; ks++) {
            const int k0 = ks * 8 + tg;
            uint32_t pa[4];
            pa[0] = __float_as_uint(Pw[gID * PPAD + k0]);
            pa[1] = __float_as_uint(Pw[(gID + 8) * PPAD + k0]);
            pa[2] = __float_as_uint(Pw[gID * PPAD + k0 + 4]);
            pa[3] = __float_as_uint(Pw[(gID + 8) * PPAD + k0 + 4]);
            #pragma unroll
            for (int nt = 0; nt < 8; nt++) {
                const float* vp = Vt + k0 * VPAD + nt * 8 + gID;
                uint32_t bfr[2] = { __float_as_uint(vp[0]), __float_as_uint(vp[4 * VPAD]) };
                mma_tf32(o[nt], pa, bfr);
            }
        }
        __syncwarp();
    }

    l0 += __shfl_xor_sync(0xffffffffu, l0, 1);
    l0 += __shfl_xor_sync(0xffffffffu, l0, 2);
    l1 += __shfl_xor_sync(0xffffffffu, l1, 1);
    l1 += __shfl_xor_sync(0xffffffffu, l1, 2);
    const float inv0 = 1.0f / l0, inv1 = 1.0f / l1;

    const int r0 = b * SEQ + q0 + wrow + gID;
    const int r1 = r0 + 8;
    bf16* O0 = O + (size_t)r0 * DMODEL + h * DHEAD + 2 * tg;
    bf16* O1 = O + (size_t)r1 * DMODEL + h * DHEAD + 2 * tg;
    #pragma unroll
    for (int nt = 0; nt < 8; nt++) {
        *(bf162*)(O0 + nt * 8) = __floats2bfloat162_rn(o[nt][0] * inv0, o[nt][1] * inv0);
        *(bf162*)(O1 + nt * 8) = __floats2bfloat162_rn(o[nt][2] * inv1, o[nt][3] * inv1);
    }
}

// ------------------------------- launcher ----------------------------------
extern "C" void kernel_launch(void* const* d_in, const int* in_sizes, int n_in,
                              void* d_out, int out_size)
{
    const float* src   = (const float*)d_in[0];
    const float* Wq    = (const float*)d_in[1];
    const float* bq    = (const float*)d_in[2];
    const float* Wk    = (const float*)d_in[3];
    const float* bk    = (const float*)d_in[4];
    const float* Wv    = (const float*)d_in[5];
    const float* bv    = (const float*)d_in[6];
    const float* Wo    = (const float*)d_in[7];
    const float* bo    = (const float*)d_in[8];
    const float* W1    = (const float*)d_in[9];
    const float* b1    = (const float*)d_in[10];
    const float* W2    = (const float*)d_in[11];
    const float* b2    = (const float*)d_in[12];
    const float* g1    = (const float*)d_in[13];
    const float* beta1 = (const float*)d_in[14];
    const float* g2    = (const float*)d_in[15];
    const float* beta2 = (const float*)d_in[16];
    float* out = (float*)d_out;

    bf16 *x, *ctx, *y, *hbuf, *wqkvT, *woT, *w1T, *w2T;
    float *qkv, *bqkv;
    cudaGetSymbolAddress((void**)&x,     g_x);
    cudaGetSymbolAddress((void**)&qkv,   g_qkv);
    cudaGetSymbolAddress((void**)&ctx,   g_ctx);
    cudaGetSymbolAddress((void**)&y,     g_y);
    cudaGetSymbolAddress((void**)&hbuf,  g_h);
    cudaGetSymbolAddress((void**)&wqkvT, g_wqkvT);
    cudaGetSymbolAddress((void**)&bqkv,  g_bqkv);
    cudaGetSymbolAddress((void**)&woT,   g_woT);
    cudaGetSymbolAddress((void**)&w1T,   g_w1T);
    cudaGetSymbolAddress((void**)&w2T,   g_w2T);

    cudaFuncSetAttribute(bf16_gemm_kernel<false,false,false>,
        cudaFuncAttributeMaxDynamicSharedMemorySize, GEMM_SMEM_BYTES);
    cudaFuncSetAttribute(bf16_gemm_kernel<false,true,false>,
        cudaFuncAttributeMaxDynamicSharedMemorySize, GEMM_SMEM_BYTES);
    cudaFuncSetAttribute(bf16_gemm_kernel<true,false,true>,
        cudaFuncAttributeMaxDynamicSharedMemorySize, GEMM_SMEM_BYTES);
    cudaFuncSetAttribute(mma_attn_kernel,
        cudaFuncAttributeMaxDynamicSharedMemorySize, ATT_SMEM_BYTES);

    // 0) weight transposes+convert ([K,N] fp32 -> [N,K] bf16), bias pack
    transpose_bf16_kernel<<<dim3(DMODEL/32, DMODEL/32), 256>>>(Wq, wqkvT,                    DMODEL, DMODEL);
    transpose_bf16_kernel<<<dim3(DMODEL/32, DMODEL/32), 256>>>(Wk, wqkvT + DMODEL*DMODEL,    DMODEL, DMODEL);
    transpose_bf16_kernel<<<dim3(DMODEL/32, DMODEL/32), 256>>>(Wv, wqkvT + 2*DMODEL*DMODEL,  DMODEL, DMODEL);
    transpose_bf16_kernel<<<dim3(DMODEL/32, DMODEL/32), 256>>>(Wo, woT,                      DMODEL, DMODEL);
    transpose_bf16_kernel<<<dim3(DFF/32,    DMODEL/32), 256>>>(W1, w1T, DMODEL, DFF);
    transpose_bf16_kernel<<<dim3(DMODEL/32, DFF/32),    256>>>(W2, w2T, DFF, DMODEL);
    pack_bias_kernel<<<(3 * DMODEL + 255) / 256, 256>>>(bq, bk, bv, bqkv);

    // 1) LN1 -> bf16
    ln_kernel<<<NTOK, 256>>>(src, g1, beta1, x);

    // 2) fused QKV projection: [8192,1024]bf16 @ [1024,3072] -> fp32
    {
        dim3 g(3 * DMODEL / 128, NTOK / 128);   // (24, 64)
        bf16_gemm_kernel<false,false,false><<<g, 256, GEMM_SMEM_BYTES>>>(
            x, wqkvT, bqkv, nullptr, qkv, 3 * DMODEL, DMODEL);
    }

    // 3) attention (tf32 mma flash) -> ctx bf16
    {
        dim3 g(SEQ / ATT_BM, NHEAD, BATCH);     // (8,16,8)
        mma_attn_kernel<<<g, 256, ATT_SMEM_BYTES>>>(qkv, ctx);
    }

    // 4) output projection + residual -> d_out (fp32)
    {
        dim3 g(DMODEL / 128, NTOK / 128);
        bf16_gemm_kernel<false,true,false><<<g, 256, GEMM_SMEM_BYTES>>>(
            ctx, woT, bo, src, out, DMODEL, DMODEL);
    }

    // 5) LN2 -> bf16
    ln_kernel<<<NTOK, 256>>>(out, g2, beta2, y);

    // 6) FFN up + ReLU -> bf16 hidden
    {
        dim3 g(DFF / 128, NTOK / 128);
        bf16_gemm_kernel<true,false,true><<<g, 256, GEMM_SMEM_BYTES>>>(
            y, w1T, b1, nullptr, hbuf, DFF, DMODEL);
    }

    // 7) FFN down + bias + residual (in-place on d_out, fp32)
    {
        dim3 g(DMODEL / 128, NTOK / 128);
        bf16_gemm_kernel<false,true,false><<<g, 256, GEMM_SMEM_BYTES>>>(
            hbuf, w2T, b2, out, out, DMODEL, DFF);
    }
}

// round 12
// speedup vs baseline: 6.2591x; 1.0832x over previous
#include <cuda_runtime.h>
#include <cuda_fp16.h>
#include <math.h>
#include <stdint.h>

// ---------------------------------------------------------------------------
// CustomEncoderLayer on GB300 (sm_103 PTX target — no 'a' features).
// R12: everything tensor-core fp16 (m16n8k16, fp32 accum): GEMMs + flash attn.
// fp16 mantissa (10 bit) ~= tf32 precision at bf16 speed; attention 2x vs tf32.
// ---------------------------------------------------------------------------

#define BATCH   8
#define SEQ     1024
#define DMODEL  1024
#define NHEAD   16
#define DHEAD   64
#define DFF     4096
#define NTOK    (BATCH * SEQ)          // 8192
#define LN_EPS  1e-5f

typedef __half  f16;
typedef __half2 f162;

// ------------------------- scratch (static device) -------------------------
__device__ f16   g_x    [NTOK * DMODEL];        // LN1 out
__device__ f16   g_qkv  [NTOK * 3 * DMODEL];    // fused q|k|v (fp16)
__device__ f16   g_ctx  [NTOK * DMODEL];        // attention out
__device__ f16   g_y    [NTOK * DMODEL];        // LN2 out
__device__ f16   g_h    [NTOK * DFF];           // FFN hidden
__device__ f16   g_wqkvT[3 * DMODEL * DMODEL];  // [3N, K]
__device__ float g_bqkv [3 * DMODEL];
__device__ f16   g_woT  [DMODEL * DMODEL];      // [N, K]
__device__ f16   g_w1T  [DFF * DMODEL];
__device__ f16   g_w2T  [DMODEL * DFF];

// ------------------------------ helpers ------------------------------------
__device__ __forceinline__ void mma_f16(float c[4], const uint32_t a[4], const uint32_t b[2]) {
    asm volatile(
        "mma.sync.aligned.m16n8k16.row.col.f32.f16.f16.f32 "
        "{%0,%1,%2,%3}, {%4,%5,%6,%7}, {%8,%9}, {%10,%11,%12,%13};"
        : "=f"(c[0]), "=f"(c[1]), "=f"(c[2]), "=f"(c[3])
        : "r"(a[0]), "r"(a[1]), "r"(a[2]), "r"(a[3]),
          "r"(b[0]), "r"(b[1]),
          "f"(c[0]), "f"(c[1]), "f"(c[2]), "f"(c[3]));
}

__device__ __forceinline__ uint32_t smem_u32(const void* p) {
    uint32_t a;
    asm("{ .reg .u64 t; cvta.to.shared.u64 t, %1; cvt.u32.u64 %0, t; }" : "=r"(a) : "l"(p));
    return a;
}
__device__ __forceinline__ uint32_t pack_h2(f16 lo, f16 hi) {
    return (uint32_t)__half_as_ushort(lo) | ((uint32_t)__half_as_ushort(hi) << 16);
}

#define CP_ASYNC16(dst, src) \
    asm volatile("cp.async.cg.shared.global [%0], [%1], 16;" :: "r"(dst), "l"(src))
#define CP_COMMIT() asm volatile("cp.async.commit_group;" ::: "memory")
#define CP_WAIT(n)  asm volatile("cp.async.wait_group %0;" :: "n"(n) : "memory")

// ------------------------------ fp16 GEMM ----------------------------------
// C[M,N] = A[M,K] @ BT[N,K]^T + bias (+res) (relu).  A,BT fp16 K-contiguous.
// BM=BN=128, BK=32, 256 thr, 8 warps (2m x 4n), warp tile 64x32,
// double-buffered cp.async, fp32 accumulate. OUTH: store fp16, else fp32.
#define GPAD 40
#define G_TILE_ELEMS (128 * GPAD)
#define G_STAGE_ELEMS (2 * G_TILE_ELEMS)
#define GEMM_SMEM_BYTES (2 * G_STAGE_ELEMS * 2)   // 40960

template<bool RELU, bool RES, bool OUTH>
__global__ void __launch_bounds__(256, 2) f16_gemm_kernel(
    const f16* __restrict__ A, const f16* __restrict__ BT,
    const float* __restrict__ bias, const float* __restrict__ res,
    void* __restrict__ Cv, int N, int K)
{
    extern __shared__ f16 smem[];
    const uint32_t sbase = smem_u32(smem);

    const int tid = threadIdx.x;
    const int wid = tid >> 5, lid = tid & 31;
    const int gID = lid >> 2, tg = lid & 3;
    const int warp_m = wid >> 2, warp_n = wid & 3;
    const int bx = blockIdx.x, by = blockIdx.y;
    const int KT = K >> 5;

    float acc[4][4][4];
    #pragma unroll
    for (int mt = 0; mt < 4; mt++)
        #pragma unroll
        for (int nt = 0; nt < 4; nt++)
            #pragma unroll
            for (int r = 0; r < 4; r++) acc[mt][nt][r] = 0.f;

    const f16* Ag0 = A  + (size_t)(by * 128) * K;
    const f16* Bg0 = BT + (size_t)(bx * 128) * K;

    auto load_stage = [&](int s, int kt) {
        const uint32_t sA = sbase + (uint32_t)(s * G_STAGE_ELEMS) * 2u;
        const uint32_t sB = sA + G_TILE_ELEMS * 2u;
        const f16* Ag = Ag0 + kt * 32;
        const f16* Bg = Bg0 + kt * 32;
        #pragma unroll
        for (int i = 0; i < 2; i++) {
            const int idx = tid + i * 256;        // 0..511
            const int r = idx >> 2, c = (idx & 3) * 8;
            CP_ASYNC16(sA + (uint32_t)(r * GPAD + c) * 2u, Ag + (size_t)r * K + c);
            CP_ASYNC16(sB + (uint32_t)(r * GPAD + c) * 2u, Bg + (size_t)r * K + c);
        }
    };

    load_stage(0, 0);
    CP_COMMIT();

    for (int kt = 0; kt < KT; kt++) {
        if (kt + 1 < KT) {
            load_stage((kt + 1) & 1, kt + 1);
            CP_COMMIT();
            CP_WAIT(1);
        } else {
            CP_WAIT(0);
        }
        __syncthreads();

        const f16* As_ = smem + (kt & 1) * G_STAGE_ELEMS;
        const f16* Bs_ = As_ + G_TILE_ELEMS;

        #pragma unroll
        for (int ks = 0; ks < 2; ks++) {
            const int kb = ks * 16 + 2 * tg;
            uint32_t afr[4][4];
            uint32_t bfr[4][2];
            #pragma unroll
            for (int mt = 0; mt < 4; mt++) {
                const f16* ap = As_ + (warp_m * 64 + mt * 16 + gID) * GPAD + kb;
                afr[mt][0] = *(const uint32_t*)ap;
                afr[mt][1] = *(const uint32_t*)(ap + 8 * GPAD);
                afr[mt][2] = *(const uint32_t*)(ap + 8);
                afr[mt][3] = *(const uint32_t*)(ap + 8 * GPAD + 8);
            }
            #pragma unroll
            for (int nt = 0; nt < 4; nt++) {
                const f16* bp = Bs_ + (warp_n * 32 + nt * 8 + gID) * GPAD + kb;
                bfr[nt][0] = *(const uint32_t*)bp;
                bfr[nt][1] = *(const uint32_t*)(bp + 8);
            }
            #pragma unroll
            for (int mt = 0; mt < 4; mt++)
                #pragma unroll
                for (int nt = 0; nt < 4; nt++)
                    mma_f16(acc[mt][nt], afr[mt], bfr[nt]);
        }
        __syncthreads();
    }

    // epilogue
    const int row_base = by * 128 + warp_m * 64 + gID;
    const int col_base = bx * 128 + warp_n * 32 + 2 * tg;
    #pragma unroll
    for (int mt = 0; mt < 4; mt++) {
        const int r0 = row_base + mt * 16;
        const int r1 = r0 + 8;
        #pragma unroll
        for (int nt = 0; nt < 4; nt++) {
            const int c = col_base + nt * 8;
            const float2 bv = *(const float2*)(bias + c);
            float2 o0 = make_float2(acc[mt][nt][0] + bv.x, acc[mt][nt][1] + bv.y);
            float2 o1 = make_float2(acc[mt][nt][2] + bv.x, acc[mt][nt][3] + bv.y);
            if (RES) {
                const float2 q0 = *(const float2*)(res + (size_t)r0 * N + c);
                const float2 q1 = *(const float2*)(res + (size_t)r1 * N + c);
                o0.x += q0.x; o0.y += q0.y;
                o1.x += q1.x; o1.y += q1.y;
            }
            if (RELU) {
                o0.x = fmaxf(o0.x, 0.f); o0.y = fmaxf(o0.y, 0.f);
                o1.x = fmaxf(o1.x, 0.f); o1.y = fmaxf(o1.y, 0.f);
            }
            if (OUTH) {
                f16* C = (f16*)Cv;
                *(f162*)(C + (size_t)r0 * N + c) = __floats2half2_rn(o0.x, o0.y);
                *(f162*)(C + (size_t)r1 * N + c) = __floats2half2_rn(o1.x, o1.y);
            } else {
                float* C = (float*)Cv;
                *(float2*)(C + (size_t)r0 * N + c) = o0;
                *(float2*)(C + (size_t)r1 * N + c) = o1;
            }
        }
    }
}

// --------------------------- weight pre-passes -----------------------------
// fp32 [R][C] -> fp16 [C][R]
__global__ __launch_bounds__(256) void transpose_f16_kernel(
    const float* __restrict__ in, f16* __restrict__ out, int R, int C)
{
    __shared__ float t[32][33];
    const int bx = blockIdx.x * 32, by = blockIdx.y * 32;
    const int tx = threadIdx.x & 31, ty = threadIdx.x >> 5;   // 32x8
    #pragma unroll
    for (int i = 0; i < 32; i += 8)
        t[ty + i][tx] = in[(size_t)(by + ty + i) * C + bx + tx];
    __syncthreads();
    #pragma unroll
    for (int i = 0; i < 32; i += 8)
        out[(size_t)(bx + ty + i) * R + by + tx] = __float2half(t[tx][ty + i]);
}

__global__ __launch_bounds__(256) void pack_bias_kernel(
    const float* __restrict__ bq, const float* __restrict__ bk,
    const float* __restrict__ bv, float* __restrict__ out)
{
    const int c = blockIdx.x * 256 + threadIdx.x;
    if (c >= 3 * DMODEL) return;
    const float* src = (c < DMODEL) ? bq : (c < 2 * DMODEL ? bk : bv);
    out[c] = src[c & (DMODEL - 1)];
}

// ------------------------------- LayerNorm ---------------------------------
// input fp32; output fp16
__global__ __launch_bounds__(256) void ln_kernel(
    const float* __restrict__ X, const float* __restrict__ gamma,
    const float* __restrict__ beta, f16* __restrict__ Y)
{
    __shared__ float red[8];
    __shared__ float sh_mu, sh_rstd;
    const int row = blockIdx.x;
    const int tid = threadIdx.x;

    const float4* xr = (const float4*)(X + (size_t)row * DMODEL);
    float4 v = xr[tid];

    float s = v.x + v.y + v.z + v.w;
    #pragma unroll
    for (int o = 16; o; o >>= 1) s += __shfl_xor_sync(0xffffffffu, s, o);
    if ((tid & 31) == 0) red[tid >> 5] = s;
    __syncthreads();
    if (tid == 0) {
        float t = 0.f;
        #pragma unroll
        for (int i = 0; i < 8; i++) t += red[i];
        sh_mu = t * (1.0f / DMODEL);
    }
    __syncthreads();
    const float mu = sh_mu;

    float4 d = make_float4(v.x - mu, v.y - mu, v.z - mu, v.w - mu);
    float sq = d.x*d.x + d.y*d.y + d.z*d.z + d.w*d.w;
    #pragma unroll
    for (int o = 16; o; o >>= 1) sq += __shfl_xor_sync(0xffffffffu, sq, o);
    __syncthreads();
    if ((tid & 31) == 0) red[tid >> 5] = sq;
    __syncthreads();
    if (tid == 0) {
        float t = 0.f;
        #pragma unroll
        for (int i = 0; i < 8; i++) t += red[i];
        sh_rstd = rsqrtf(t * (1.0f / DMODEL) + LN_EPS);
    }
    __syncthreads();
    const float rstd = sh_rstd;

    float4 gv = ((const float4*)gamma)[tid];
    float4 bv = ((const float4*)beta)[tid];
    float4 o;
    o.x = d.x * rstd * gv.x + bv.x;
    o.y = d.y * rstd * gv.y + bv.y;
    o.z = d.z * rstd * gv.z + bv.z;
    o.w = d.w * rstd * gv.w + bv.w;
    f162* yr = (f162*)(Y + (size_t)row * DMODEL);
    yr[2 * tid + 0] = __floats2half2_rn(o.x, o.y);
    yr[2 * tid + 1] = __floats2half2_rn(o.z, o.w);
}

// ---------------------- fp16 mma flash attention ---------------------------
// QKV fused fp16: row stride 3*DMODEL; q@+0, k@+DMODEL, v@+2*DMODEL.
// CTA 256 thr / 8 warps, 128 queries, 64-key tiles double-buffered cp.async.
// S = Q·K^T and O += P·V both via m16n8k16 fp16 mma (fp32 accum).
#define QKV_LD   (3 * DMODEL)
#define ATT_BM   128
#define ATT_BN   64
#define KPAD     72                         // halfs; rows 144B apart -> 16B-distinct mod 128
#define VPAD     72
#define PPAD     72
#define ATT_K_ELEMS (2 * ATT_BN * KPAD)     // 9216 halfs
#define ATT_V_ELEMS (2 * ATT_BN * VPAD)
#define ATT_P_ELEMS (ATT_BM * PPAD)
#define ATT_SMEM_BYTES ((ATT_K_ELEMS + ATT_V_ELEMS + ATT_P_ELEMS) * 2)   // 55296

__global__ void __launch_bounds__(256, 2) mma_attn_kernel(
    const f16* __restrict__ QKV, f16* __restrict__ O)
{
    extern __shared__ f16 smh[];
    f16* Ksm = smh;
    f16* Vsm = smh + ATT_K_ELEMS;
    f16* Psm = Vsm + ATT_V_ELEMS;

    const int tid = threadIdx.x;
    const int wid = tid >> 5, lid = tid & 31;
    const int gID = lid >> 2, tg = lid & 3;
    const int b = blockIdx.z, h = blockIdx.y;
    const int q0 = blockIdx.x * ATT_BM;
    const int wrow = wid * 16;

    const f16* Qb = QKV + (size_t)(b * SEQ + q0 + wrow) * QKV_LD + h * DHEAD;
    const f16* Kb = QKV + (size_t)(b * SEQ) * QKV_LD + DMODEL + h * DHEAD;
    const f16* Vb = Kb + DMODEL;

    // Q a-frags: scale*log2e folded (fp32 multiply, round once to fp16)
    const float qscale = 0.125f * 1.4426950408889634f;
    uint32_t qa[4][4];
    #pragma unroll
    for (int ks = 0; ks < 4; ks++) {
        const int k0 = ks * 16 + 2 * tg;
        #pragma unroll
        for (int half8 = 0; half8 < 2; half8++) {      // +0 / +8 in k
            const int kk = k0 + half8 * 8;
            const float a0 = __half2float(Qb[(size_t)gID * QKV_LD + kk])     * qscale;
            const float a1 = __half2float(Qb[(size_t)gID * QKV_LD + kk + 1]) * qscale;
            const float b0 = __half2float(Qb[(size_t)(gID + 8) * QKV_LD + kk])     * qscale;
            const float b1 = __half2float(Qb[(size_t)(gID + 8) * QKV_LD + kk + 1]) * qscale;
            f162 ra = __floats2half2_rn(a0, a1);
            f162 rb = __floats2half2_rn(b0, b1);
            qa[ks][half8 * 2 + 0] = *(uint32_t*)&ra;   // rows gID
            qa[ks][half8 * 2 + 1] = *(uint32_t*)&rb;   // rows gID+8
        }
        // reorder to a-frag convention {r0,k0 | r1,k0 | r0,k8 | r1,k8}
        uint32_t t1 = qa[ks][1], t2 = qa[ks][2];
        qa[ks][1] = t2; qa[ks][2] = t1;
        // now qa = {gID,k0}, {gID,k8}... fix below
    }
    // NOTE on ordering: a-frag regs must be {row gID,k0-1},{row gID+8,k0-1},
    // {row gID,k8-9},{row gID+8,k8-9}. Rebuild cleanly:
    #pragma unroll
    for (int ks = 0; ks < 4; ks++) {
        const int k0 = ks * 16 + 2 * tg;
        float a, c;
        a = __half2float(Qb[(size_t)gID * QKV_LD + k0]) * qscale;
        c = __half2float(Qb[(size_t)gID * QKV_LD + k0 + 1]) * qscale;
        f162 r0 = __floats2half2_rn(a, c);
        a = __half2float(Qb[(size_t)(gID + 8) * QKV_LD + k0]) * qscale;
        c = __half2float(Qb[(size_t)(gID + 8) * QKV_LD + k0 + 1]) * qscale;
        f162 r1 = __floats2half2_rn(a, c);
        a = __half2float(Qb[(size_t)gID * QKV_LD + k0 + 8]) * qscale;
        c = __half2float(Qb[(size_t)gID * QKV_LD + k0 + 9]) * qscale;
        f162 r2 = __floats2half2_rn(a, c);
        a = __half2float(Qb[(size_t)(gID + 8) * QKV_LD + k0 + 8]) * qscale;
        c = __half2float(Qb[(size_t)(gID + 8) * QKV_LD + k0 + 9]) * qscale;
        f162 r3 = __floats2half2_rn(a, c);
        qa[ks][0] = *(uint32_t*)&r0;
        qa[ks][1] = *(uint32_t*)&r1;
        qa[ks][2] = *(uint32_t*)&r2;
        qa[ks][3] = *(uint32_t*)&r3;
    }

    float o[8][4];
    #pragma unroll
    for (int nt = 0; nt < 8; nt++)
        #pragma unroll
        for (int r = 0; r < 4; r++) o[nt][r] = 0.f;
    float m0 = -1e30f, m1 = -1e30f, l0 = 0.f, l1 = 0.f;

    const uint32_t kbase = smem_u32(Ksm);
    const uint32_t vbase = smem_u32(Vsm);

    auto load_kv = [&](int jt) {
        const int s = jt & 1;
        const f16* Kg = Kb + (size_t)(jt * ATT_BN) * QKV_LD;
        const f16* Vg = Vb + (size_t)(jt * ATT_BN) * QKV_LD;
        const uint32_t kdst = kbase + (uint32_t)(s * ATT_BN * KPAD) * 2u;
        const uint32_t vdst = vbase + (uint32_t)(s * ATT_BN * VPAD) * 2u;
        #pragma unroll
        for (int i = 0; i < 2; i++) {
            const int c = tid + i * 256;          // 0..511
            const int r = c >> 3, col = (c & 7) * 8;
            CP_ASYNC16(kdst + (uint32_t)(r * KPAD + col) * 2u,
                       Kg + (size_t)r * QKV_LD + col);
            CP_ASYNC16(vdst + (uint32_t)(r * VPAD + col) * 2u,
                       Vg + (size_t)r * QKV_LD + col);
        }
    };

    load_kv(0);
    CP_COMMIT();

    const int NT = SEQ / ATT_BN;   // 16
    f16* Pw = Psm + wrow * PPAD;

    for (int jt = 0; jt < NT; jt++) {
        CP_WAIT(0);
        __syncthreads();
        if (jt + 1 < NT) { load_kv(jt + 1); CP_COMMIT(); }

        const f16* Kt = Ksm + (jt & 1) * ATT_BN * KPAD;
        const f16* Vt = Vsm + (jt & 1) * ATT_BN * VPAD;

        // S = Q K^T (log2 domain)
        float s[8][4];
        #pragma unroll
        for (int nt = 0; nt < 8; nt++)
            #pragma unroll
            for (int r = 0; r < 4; r++) s[nt][r] = 0.f;

        #pragma unroll
        for (int ks = 0; ks < 4; ks++) {
            const int kb = ks * 16 + 2 * tg;
            #pragma unroll
            for (int nt = 0; nt < 8; nt++) {
                const f16* kp = Kt + (nt * 8 + gID) * KPAD + kb;
                uint32_t bfr[2] = { *(const uint32_t*)kp, *(const uint32_t*)(kp + 8) };
                mma_f16(s[nt], qa[ks], bfr);
            }
        }

        // online softmax (rows gID / gID+8)
        float mx0 = s[0][0], mx1 = s[0][2];
        #pragma unroll
        for (int nt = 0; nt < 8; nt++) {
            mx0 = fmaxf(mx0, fmaxf(s[nt][0], s[nt][1]));
            mx1 = fmaxf(mx1, fmaxf(s[nt][2], s[nt][3]));
        }
        mx0 = fmaxf(mx0, __shfl_xor_sync(0xffffffffu, mx0, 1));
        mx0 = fmaxf(mx0, __shfl_xor_sync(0xffffffffu, mx0, 2));
        mx1 = fmaxf(mx1, __shfl_xor_sync(0xffffffffu, mx1, 1));
        mx1 = fmaxf(mx1, __shfl_xor_sync(0xffffffffu, mx1, 2));

        const float mn0 = fmaxf(m0, mx0), mn1 = fmaxf(m1, mx1);
        const float a0 = exp2f(m0 - mn0), a1 = exp2f(m1 - mn1);
        m0 = mn0; m1 = mn1;

        float ls0 = 0.f, ls1 = 0.f;
        #pragma unroll
        for (int nt = 0; nt < 8; nt++) {
            const float p0 = exp2f(s[nt][0] - m0);
            const float p1 = exp2f(s[nt][1] - m0);
            const float p2 = exp2f(s[nt][2] - m1);
            const float p3 = exp2f(s[nt][3] - m1);
            ls0 += p0 + p1;
            ls1 += p2 + p3;
            *(f162*)(Pw + gID * PPAD + nt * 8 + 2 * tg)       = __floats2half2_rn(p0, p1);
            *(f162*)(Pw + (gID + 8) * PPAD + nt * 8 + 2 * tg) = __floats2half2_rn(p2, p3);
            o[nt][0] *= a0; o[nt][1] *= a0;
            o[nt][2] *= a1; o[nt][3] *= a1;
        }
        l0 = l0 * a0 + ls0;
        l1 = l1 * a1 + ls1;
        __syncwarp();

        // O += P V  (contraction over keys, 4 x k16)
        #pragma unroll
        for (int ks = 0; ks < 4; ks++) {
            const int k0 = ks * 16 + 2 * tg;
            uint32_t pa[4];
            pa[0] = *(const uint32_t*)(Pw + gID * PPAD + k0);
            pa[1] = *(const uint32_t*)(Pw + (gID + 8) * PPAD + k0);
            pa[2] = *(const uint32_t*)(Pw + gID * PPAD + k0 + 8);
            pa[3] = *(const uint32_t*)(Pw + (gID + 8) * PPAD + k0 + 8);
            #pragma unroll
            for (int nt = 0; nt < 8; nt++) {
                const int d = nt * 8 + gID;
                uint32_t bfr[2];
                bfr[0] = pack_h2(Vt[(size_t)k0 * VPAD + d],       Vt[(size_t)(k0 + 1) * VPAD + d]);
                bfr[1] = pack_h2(Vt[(size_t)(k0 + 8) * VPAD + d], Vt[(size_t)(k0 + 9) * VPAD + d]);
                mma_f16(o[nt], pa, bfr);
            }
        }
        __syncwarp();
    }

    // finalize
    l0 += __shfl_xor_sync(0xffffffffu, l0, 1);
    l0 += __shfl_xor_sync(0xffffffffu, l0, 2);
    l1 += __shfl_xor_sync(0xffffffffu, l1, 1);
    l1 += __shfl_xor_sync(0xffffffffu, l1, 2);
    const float inv0 = 1.0f / l0, inv1 = 1.0f / l1;

    const int r0 = b * SEQ + q0 + wrow + gID;
    const int r1 = r0 + 8;
    f16* O0 = O + (size_t)r0 * DMODEL + h * DHEAD + 2 * tg;
    f16* O1 = O + (size_t)r1 * DMODEL + h * DHEAD + 2 * tg;
    #pragma unroll
    for (int nt = 0; nt < 8; nt++) {
        *(f162*)(O0 + nt * 8) = __floats2half2_rn(o[nt][0] * inv0, o[nt][1] * inv0);
        *(f162*)(O1 + nt * 8) = __floats2half2_rn(o[nt][2] * inv1, o[nt][3] * inv1);
    }
}

// ------------------------------- launcher ----------------------------------
extern "C" void kernel_launch(void* const* d_in, const int* in_sizes, int n_in,
                              void* d_out, int out_size)
{
    const float* src   = (const float*)d_in[0];
    const float* Wq    = (const float*)d_in[1];
    const float* bq    = (const float*)d_in[2];
    const float* Wk    = (const float*)d_in[3];
    const float* bk    = (const float*)d_in[4];
    const float* Wv    = (const float*)d_in[5];
    const float* bv    = (const float*)d_in[6];
    const float* Wo    = (const float*)d_in[7];
    const float* bo    = (const float*)d_in[8];
    const float* W1    = (const float*)d_in[9];
    const float* b1    = (const float*)d_in[10];
    const float* W2    = (const float*)d_in[11];
    const float* b2    = (const float*)d_in[12];
    const float* g1    = (const float*)d_in[13];
    const float* beta1 = (const float*)d_in[14];
    const float* g2    = (const float*)d_in[15];
    const float* beta2 = (const float*)d_in[16];
    float* out = (float*)d_out;

    f16 *x, *qkv, *ctx, *y, *hbuf, *wqkvT, *woT, *w1T, *w2T;
    float *bqkv;
    cudaGetSymbolAddress((void**)&x,     g_x);
    cudaGetSymbolAddress((void**)&qkv,   g_qkv);
    cudaGetSymbolAddress((void**)&ctx,   g_ctx);
    cudaGetSymbolAddress((void**)&y,     g_y);
    cudaGetSymbolAddress((void**)&hbuf,  g_h);
    cudaGetSymbolAddress((void**)&wqkvT, g_wqkvT);
    cudaGetSymbolAddress((void**)&bqkv,  g_bqkv);
    cudaGetSymbolAddress((void**)&woT,   g_woT);
    cudaGetSymbolAddress((void**)&w1T,   g_w1T);
    cudaGetSymbolAddress((void**)&w2T,   g_w2T);

    cudaFuncSetAttribute(f16_gemm_kernel<false,false,true>,
        cudaFuncAttributeMaxDynamicSharedMemorySize, GEMM_SMEM_BYTES);
    cudaFuncSetAttribute(f16_gemm_kernel<false,true,false>,
        cudaFuncAttributeMaxDynamicSharedMemorySize, GEMM_SMEM_BYTES);
    cudaFuncSetAttribute(f16_gemm_kernel<true,false,true>,
        cudaFuncAttributeMaxDynamicSharedMemorySize, GEMM_SMEM_BYTES);
    cudaFuncSetAttribute(mma_attn_kernel,
        cudaFuncAttributeMaxDynamicSharedMemorySize, ATT_SMEM_BYTES);

    // 0) weight transposes+convert ([K,N] fp32 -> [N,K] fp16), bias pack
    transpose_f16_kernel<<<dim3(DMODEL/32, DMODEL/32), 256>>>(Wq, wqkvT,                   DMODEL, DMODEL);
    transpose_f16_kernel<<<dim3(DMODEL/32, DMODEL/32), 256>>>(Wk, wqkvT + DMODEL*DMODEL,   DMODEL, DMODEL);
    transpose_f16_kernel<<<dim3(DMODEL/32, DMODEL/32), 256>>>(Wv, wqkvT + 2*DMODEL*DMODEL, DMODEL, DMODEL);
    transpose_f16_kernel<<<dim3(DMODEL/32, DMODEL/32), 256>>>(Wo, woT,                     DMODEL, DMODEL);
    transpose_f16_kernel<<<dim3(DFF/32,    DMODEL/32), 256>>>(W1, w1T, DMODEL, DFF);
    transpose_f16_kernel<<<dim3(DMODEL/32, DFF/32),    256>>>(W2, w2T, DFF, DMODEL);
    pack_bias_kernel<<<(3 * DMODEL + 255) / 256, 256>>>(bq, bk, bv, bqkv);

    // 1) LN1 -> fp16
    ln_kernel<<<NTOK, 256>>>(src, g1, beta1, x);

    // 2) fused QKV projection -> fp16
    {
        dim3 g(3 * DMODEL / 128, NTOK / 128);   // (24, 64)
        f16_gemm_kernel<false,false,true><<<g, 256, GEMM_SMEM_BYTES>>>(
            x, wqkvT, bqkv, nullptr, qkv, 3 * DMODEL, DMODEL);
    }

    // 3) attention (fp16 mma flash) -> ctx fp16
    {
        dim3 g(SEQ / ATT_BM, NHEAD, BATCH);     // (8,16,8)
        mma_attn_kernel<<<g, 256, ATT_SMEM_BYTES>>>(qkv, ctx);
    }

    // 4) output projection + residual -> d_out (fp32)
    {
        dim3 g(DMODEL / 128, NTOK / 128);
        f16_gemm_kernel<false,true,false><<<g, 256, GEMM_SMEM_BYTES>>>(
            ctx, woT, bo, src, out, DMODEL, DMODEL);
    }

    // 5) LN2 -> fp16
    ln_kernel<<<NTOK, 256>>>(out, g2, beta2, y);

    // 6) FFN up + ReLU -> fp16 hidden
    {
        dim3 g(DFF / 128, NTOK / 128);
        f16_gemm_kernel<true,false,true><<<g, 256, GEMM_SMEM_BYTES>>>(
            y, w1T, b1, nullptr, hbuf, DFF, DMODEL);
    }

    // 7) FFN down + bias + residual (in-place on d_out, fp32)
    {
        dim3 g(DMODEL / 128, NTOK / 128);
        f16_gemm_kernel<false,true,false><<<g, 256, GEMM_SMEM_BYTES>>>(
            hbuf, w2T, b2, out, out, DMODEL, DFF);
    }
}

// round 13
// speedup vs baseline: 7.0788x; 1.1310x over previous
#include <cuda_runtime.h>
#include <cuda_fp16.h>
#include <math.h>
#include <stdint.h>

// ---------------------------------------------------------------------------
// CustomEncoderLayer on GB300 (sm_103 PTX target — no 'a' features).
// R13: fp16 mma GEMMs with ldmatrix fragment loads + 4-stage cp.async
// pipeline; fp16 mma flash attention (unchanged from R12).
// ---------------------------------------------------------------------------

#define BATCH   8
#define SEQ     1024
#define DMODEL  1024
#define NHEAD   16
#define DHEAD   64
#define DFF     4096
#define NTOK    (BATCH * SEQ)          // 8192
#define LN_EPS  1e-5f

typedef __half  f16;
typedef __half2 f162;

// ------------------------- scratch (static device) -------------------------
__device__ f16   g_x    [NTOK * DMODEL];        // LN1 out
__device__ f16   g_qkv  [NTOK * 3 * DMODEL];    // fused q|k|v (fp16)
__device__ f16   g_ctx  [NTOK * DMODEL];        // attention out
__device__ f16   g_y    [NTOK * DMODEL];        // LN2 out
__device__ f16   g_h    [NTOK * DFF];           // FFN hidden
__device__ f16   g_wqkvT[3 * DMODEL * DMODEL];  // [3N, K]
__device__ float g_bqkv [3 * DMODEL];
__device__ f16   g_woT  [DMODEL * DMODEL];      // [N, K]
__device__ f16   g_w1T  [DFF * DMODEL];
__device__ f16   g_w2T  [DMODEL * DFF];

// ------------------------------ helpers ------------------------------------
__device__ __forceinline__ void mma_f16(float c[4], const uint32_t a[4], const uint32_t b[2]) {
    asm volatile(
        "mma.sync.aligned.m16n8k16.row.col.f32.f16.f16.f32 "
        "{%0,%1,%2,%3}, {%4,%5,%6,%7}, {%8,%9}, {%10,%11,%12,%13};"
        : "=f"(c[0]), "=f"(c[1]), "=f"(c[2]), "=f"(c[3])
        : "r"(a[0]), "r"(a[1]), "r"(a[2]), "r"(a[3]),
          "r"(b[0]), "r"(b[1]),
          "f"(c[0]), "f"(c[1]), "f"(c[2]), "f"(c[3]));
}

__device__ __forceinline__ uint32_t smem_u32(const void* p) {
    uint32_t a;
    asm("{ .reg .u64 t; cvta.to.shared.u64 t, %1; cvt.u32.u64 %0, t; }" : "=r"(a) : "l"(p));
    return a;
}
__device__ __forceinline__ uint32_t pack_h2(f16 lo, f16 hi) {
    return (uint32_t)__half_as_ushort(lo) | ((uint32_t)__half_as_ushort(hi) << 16);
}

#define LDSM_X4(r0, r1, r2, r3, addr) \
    asm volatile("ldmatrix.sync.aligned.m8n8.x4.shared.b16 {%0,%1,%2,%3}, [%4];" \
        : "=r"(r0), "=r"(r1), "=r"(r2), "=r"(r3) : "r"(addr))

#define CP_ASYNC16(dst, src) \
    asm volatile("cp.async.cg.shared.global [%0], [%1], 16;" :: "r"(dst), "l"(src))
#define CP_COMMIT() asm volatile("cp.async.commit_group;" ::: "memory")
#define CP_WAIT(n)  asm volatile("cp.async.wait_group %0;" :: "n"(n) : "memory")

// ------------------------------ fp16 GEMM ----------------------------------
// C[M,N] = A[M,K] @ BT[N,K]^T + bias (+res) (relu).  A,BT fp16 K-contiguous.
// BM=BN=128, BK=32, 256 thr, 8 warps (2m x 4n), warp tile 64x32.
// 4-stage cp.async pipeline; ldmatrix.x4 fragment loads; fp32 accumulate.
#define NSTAGE 4
#define GPAD 40
#define G_TILE_ELEMS (128 * GPAD)                  // 5120 halfs per operand
#define G_STAGE_ELEMS (2 * G_TILE_ELEMS)
#define GEMM_SMEM_BYTES (NSTAGE * G_STAGE_ELEMS * 2)   // 81920

template<bool RELU, bool RES, bool OUTH>
__global__ void __launch_bounds__(256, 2) f16_gemm_kernel(
    const f16* __restrict__ A, const f16* __restrict__ BT,
    const float* __restrict__ bias, const float* __restrict__ res,
    void* __restrict__ Cv, int N, int K)
{
    extern __shared__ f16 smem[];
    const uint32_t sbase = smem_u32(smem);

    const int tid = threadIdx.x;
    const int wid = tid >> 5, lid = tid & 31;
    const int gID = lid >> 2, tg = lid & 3;
    const int warp_m = wid >> 2, warp_n = wid & 3;
    const int bx = blockIdx.x, by = blockIdx.y;
    const int KT = K >> 5;

    float acc[4][4][4];
    #pragma unroll
    for (int mt = 0; mt < 4; mt++)
        #pragma unroll
        for (int nt = 0; nt < 4; nt++)
            #pragma unroll
            for (int r = 0; r < 4; r++) acc[mt][nt][r] = 0.f;

    const f16* Ag0 = A  + (size_t)(by * 128) * K;
    const f16* Bg0 = BT + (size_t)(bx * 128) * K;

    auto load_stage = [&](int s, int kt) {
        const uint32_t sA = sbase + (uint32_t)(s * G_STAGE_ELEMS) * 2u;
        const uint32_t sB = sA + G_TILE_ELEMS * 2u;
        const f16* Ag = Ag0 + kt * 32;
        const f16* Bg = Bg0 + kt * 32;
        #pragma unroll
        for (int i = 0; i < 2; i++) {
            const int idx = tid + i * 256;        // 0..511
            const int r = idx >> 2, c = (idx & 3) * 8;
            CP_ASYNC16(sA + (uint32_t)(r * GPAD + c) * 2u, Ag + (size_t)r * K + c);
            CP_ASYNC16(sB + (uint32_t)(r * GPAD + c) * 2u, Bg + (size_t)r * K + c);
        }
    };

    // ldmatrix lane-address bases (stage-0 offsets; add stage/ks offsets in loop)
    // A tile (x4 -> a-frag m16k16): lanes 0-15 rows 0-15 @kb, 16-31 rows @kb+8
    const int lrowA = lid & 15;
    const int lcolA = (lid >> 4) * 8;
    uint32_t aoff[4];
    #pragma unroll
    for (int mt = 0; mt < 4; mt++)
        aoff[mt] = sbase + (uint32_t)(((warp_m * 64 + mt * 16 + lrowA) * GPAD + lcolA) * 2);
    // B tile (x4 -> b-frags for nt pair): lanes 0-7 n0-7@kb, 8-15 n0-7@kb+8,
    // 16-23 n8-15@kb, 24-31 n8-15@kb+8
    const int lrowB = (lid & 7) + ((lid >> 4) << 3);
    const int lcolB = ((lid >> 3) & 1) * 8;
    uint32_t boff[2];
    #pragma unroll
    for (int p = 0; p < 2; p++)
        boff[p] = sbase + (uint32_t)((G_TILE_ELEMS + (warp_n * 32 + p * 16 + lrowB) * GPAD + lcolB) * 2);

    // prologue: stages 0..2
    #pragma unroll
    for (int p = 0; p < NSTAGE - 1; p++) {
        load_stage(p, p);
        CP_COMMIT();
    }

    for (int kt = 0; kt < KT; kt++) {
        CP_WAIT(2);
        __syncthreads();
        if (kt + NSTAGE - 1 < KT) load_stage((kt + NSTAGE - 1) & (NSTAGE - 1), kt + NSTAGE - 1);
        CP_COMMIT();

        const uint32_t soff = (uint32_t)((kt & (NSTAGE - 1)) * G_STAGE_ELEMS * 2);

        #pragma unroll
        for (int ks = 0; ks < 2; ks++) {
            const uint32_t ko = soff + ks * 32;   // ks*16 halfs
            uint32_t afr[4][4];
            uint32_t bfr[4][2];
            #pragma unroll
            for (int mt = 0; mt < 4; mt++)
                LDSM_X4(afr[mt][0], afr[mt][1], afr[mt][2], afr[mt][3], aoff[mt] + ko);
            #pragma unroll
            for (int p = 0; p < 2; p++) {
                uint32_t t0, t1, t2, t3;
                LDSM_X4(t0, t1, t2, t3, boff[p] + ko);
                bfr[2 * p][0] = t0; bfr[2 * p][1] = t1;
                bfr[2 * p + 1][0] = t2; bfr[2 * p + 1][1] = t3;
            }
            #pragma unroll
            for (int mt = 0; mt < 4; mt++)
                #pragma unroll
                for (int nt = 0; nt < 4; nt++)
                    mma_f16(acc[mt][nt], afr[mt], bfr[nt]);
        }
    }

    // epilogue
    const int row_base = by * 128 + warp_m * 64 + gID;
    const int col_base = bx * 128 + warp_n * 32 + 2 * tg;
    #pragma unroll
    for (int mt = 0; mt < 4; mt++) {
        const int r0 = row_base + mt * 16;
        const int r1 = r0 + 8;
        #pragma unroll
        for (int nt = 0; nt < 4; nt++) {
            const int c = col_base + nt * 8;
            const float2 bv = *(const float2*)(bias + c);
            float2 o0 = make_float2(acc[mt][nt][0] + bv.x, acc[mt][nt][1] + bv.y);
            float2 o1 = make_float2(acc[mt][nt][2] + bv.x, acc[mt][nt][3] + bv.y);
            if (RES) {
                const float2 q0 = *(const float2*)(res + (size_t)r0 * N + c);
                const float2 q1 = *(const float2*)(res + (size_t)r1 * N + c);
                o0.x += q0.x; o0.y += q0.y;
                o1.x += q1.x; o1.y += q1.y;
            }
            if (RELU) {
                o0.x = fmaxf(o0.x, 0.f); o0.y = fmaxf(o0.y, 0.f);
                o1.x = fmaxf(o1.x, 0.f); o1.y = fmaxf(o1.y, 0.f);
            }
            if (OUTH) {
                f16* C = (f16*)Cv;
                *(f162*)(C + (size_t)r0 * N + c) = __floats2half2_rn(o0.x, o0.y);
                *(f162*)(C + (size_t)r1 * N + c) = __floats2half2_rn(o1.x, o1.y);
            } else {
                float* C = (float*)Cv;
                *(float2*)(C + (size_t)r0 * N + c) = o0;
                *(float2*)(C + (size_t)r1 * N + c) = o1;
            }
        }
    }
}

// --------------------------- weight pre-passes -----------------------------
// fp32 [R][C] -> fp16 [C][R]
__global__ __launch_bounds__(256) void transpose_f16_kernel(
    const float* __restrict__ in, f16* __restrict__ out, int R, int C)
{
    __shared__ float t[32][33];
    const int bx = blockIdx.x * 32, by = blockIdx.y * 32;
    const int tx = threadIdx.x & 31, ty = threadIdx.x >> 5;   // 32x8
    #pragma unroll
    for (int i = 0; i < 32; i += 8)
        t[ty + i][tx] = in[(size_t)(by + ty + i) * C + bx + tx];
    __syncthreads();
    #pragma unroll
    for (int i = 0; i < 32; i += 8)
        out[(size_t)(bx + ty + i) * R + by + tx] = __float2half(t[tx][ty + i]);
}

__global__ __launch_bounds__(256) void pack_bias_kernel(
    const float* __restrict__ bq, const float* __restrict__ bk,
    const float* __restrict__ bv, float* __restrict__ out)
{
    const int c = blockIdx.x * 256 + threadIdx.x;
    if (c >= 3 * DMODEL) return;
    const float* src = (c < DMODEL) ? bq : (c < 2 * DMODEL ? bk : bv);
    out[c] = src[c & (DMODEL - 1)];
}

// ------------------------------- LayerNorm ---------------------------------
// input fp32; output fp16
__global__ __launch_bounds__(256) void ln_kernel(
    const float* __restrict__ X, const float* __restrict__ gamma,
    const float* __restrict__ beta, f16* __restrict__ Y)
{
    __shared__ float red[8];
    __shared__ float sh_mu, sh_rstd;
    const int row = blockIdx.x;
    const int tid = threadIdx.x;

    const float4* xr = (const float4*)(X + (size_t)row * DMODEL);
    float4 v = xr[tid];

    float s = v.x + v.y + v.z + v.w;
    #pragma unroll
    for (int o = 16; o; o >>= 1) s += __shfl_xor_sync(0xffffffffu, s, o);
    if ((tid & 31) == 0) red[tid >> 5] = s;
    __syncthreads();
    if (tid == 0) {
        float t = 0.f;
        #pragma unroll
        for (int i = 0; i < 8; i++) t += red[i];
        sh_mu = t * (1.0f / DMODEL);
    }
    __syncthreads();
    const float mu = sh_mu;

    float4 d = make_float4(v.x - mu, v.y - mu, v.z - mu, v.w - mu);
    float sq = d.x*d.x + d.y*d.y + d.z*d.z + d.w*d.w;
    #pragma unroll
    for (int o = 16; o; o >>= 1) sq += __shfl_xor_sync(0xffffffffu, sq, o);
    __syncthreads();
    if ((tid & 31) == 0) red[tid >> 5] = sq;
    __syncthreads();
    if (tid == 0) {
        float t = 0.f;
        #pragma unroll
        for (int i = 0; i < 8; i++) t += red[i];
        sh_rstd = rsqrtf(t * (1.0f / DMODEL) + LN_EPS);
    }
    __syncthreads();
    const float rstd = sh_rstd;

    float4 gv = ((const float4*)gamma)[tid];
    float4 bv = ((const float4*)beta)[tid];
    float4 o;
    o.x = d.x * rstd * gv.x + bv.x;
    o.y = d.y * rstd * gv.y + bv.y;
    o.z = d.z * rstd * gv.z + bv.z;
    o.w = d.w * rstd * gv.w + bv.w;
    f162* yr = (f162*)(Y + (size_t)row * DMODEL);
    yr[2 * tid + 0] = __floats2half2_rn(o.x, o.y);
    yr[2 * tid + 1] = __floats2half2_rn(o.z, o.w);
}

// ---------------------- fp16 mma flash attention ---------------------------
// QKV fused fp16: row stride 3*DMODEL; q@+0, k@+DMODEL, v@+2*DMODEL.
#define QKV_LD   (3 * DMODEL)
#define ATT_BM   128
#define ATT_BN   64
#define KPAD     72
#define VPAD     72
#define PPAD     72
#define ATT_K_ELEMS (2 * ATT_BN * KPAD)
#define ATT_V_ELEMS (2 * ATT_BN * VPAD)
#define ATT_P_ELEMS (ATT_BM * PPAD)
#define ATT_SMEM_BYTES ((ATT_K_ELEMS + ATT_V_ELEMS + ATT_P_ELEMS) * 2)   // 55296

__global__ void __launch_bounds__(256, 2) mma_attn_kernel(
    const f16* __restrict__ QKV, f16* __restrict__ O)
{
    extern __shared__ f16 smh[];
    f16* Ksm = smh;
    f16* Vsm = smh + ATT_K_ELEMS;
    f16* Psm = Vsm + ATT_V_ELEMS;

    const int tid = threadIdx.x;
    const int wid = tid >> 5, lid = tid & 31;
    const int gID = lid >> 2, tg = lid & 3;
    const int b = blockIdx.z, h = blockIdx.y;
    const int q0 = blockIdx.x * ATT_BM;
    const int wrow = wid * 16;

    const f16* Qb = QKV + (size_t)(b * SEQ + q0 + wrow) * QKV_LD + h * DHEAD;
    const f16* Kb = QKV + (size_t)(b * SEQ) * QKV_LD + DMODEL + h * DHEAD;
    const f16* Vb = Kb + DMODEL;

    // Q a-frags: scale*log2e folded (fp32 multiply, round once to fp16)
    const float qscale = 0.125f * 1.4426950408889634f;
    uint32_t qa[4][4];
    #pragma unroll
    for (int ks = 0; ks < 4; ks++) {
        const int k0 = ks * 16 + 2 * tg;
        float a, c;
        a = __half2float(Qb[(size_t)gID * QKV_LD + k0]) * qscale;
        c = __half2float(Qb[(size_t)gID * QKV_LD + k0 + 1]) * qscale;
        f162 r0 = __floats2half2_rn(a, c);
        a = __half2float(Qb[(size_t)(gID + 8) * QKV_LD + k0]) * qscale;
        c = __half2float(Qb[(size_t)(gID + 8) * QKV_LD + k0 + 1]) * qscale;
        f162 r1 = __floats2half2_rn(a, c);
        a = __half2float(Qb[(size_t)gID * QKV_LD + k0 + 8]) * qscale;
        c = __half2float(Qb[(size_t)gID * QKV_LD + k0 + 9]) * qscale;
        f162 r2 = __floats2half2_rn(a, c);
        a = __half2float(Qb[(size_t)(gID + 8) * QKV_LD + k0 + 8]) * qscale;
        c = __half2float(Qb[(size_t)(gID + 8) * QKV_LD + k0 + 9]) * qscale;
        f162 r3 = __floats2half2_rn(a, c);
        qa[ks][0] = *(uint32_t*)&r0;
        qa[ks][1] = *(uint32_t*)&r1;
        qa[ks][2] = *(uint32_t*)&r2;
        qa[ks][3] = *(uint32_t*)&r3;
    }

    float o[8][4];
    #pragma unroll
    for (int nt = 0; nt < 8; nt++)
        #pragma unroll
        for (int r = 0; r < 4; r++) o[nt][r] = 0.f;
    float m0 = -1e30f, m1 = -1e30f, l0 = 0.f, l1 = 0.f;

    const uint32_t kbase = smem_u32(Ksm);
    const uint32_t vbase = smem_u32(Vsm);

    auto load_kv = [&](int jt) {
        const int s = jt & 1;
        const f16* Kg = Kb + (size_t)(jt * ATT_BN) * QKV_LD;
        const f16* Vg = Vb + (size_t)(jt * ATT_BN) * QKV_LD;
        const uint32_t kdst = kbase + (uint32_t)(s * ATT_BN * KPAD) * 2u;
        const uint32_t vdst = vbase + (uint32_t)(s * ATT_BN * VPAD) * 2u;
        #pragma unroll
        for (int i = 0; i < 2; i++) {
            const int c = tid + i * 256;          // 0..511
            const int r = c >> 3, col = (c & 7) * 8;
            CP_ASYNC16(kdst + (uint32_t)(r * KPAD + col) * 2u,
                       Kg + (size_t)r * QKV_LD + col);
            CP_ASYNC16(vdst + (uint32_t)(r * VPAD + col) * 2u,
                       Vg + (size_t)r * QKV_LD + col);
        }
    };

    load_kv(0);
    CP_COMMIT();

    const int NT = SEQ / ATT_BN;   // 16
    f16* Pw = Psm + wrow * PPAD;

    for (int jt = 0; jt < NT; jt++) {
        CP_WAIT(0);
        __syncthreads();
        if (jt + 1 < NT) { load_kv(jt + 1); CP_COMMIT(); }

        const f16* Kt = Ksm + (jt & 1) * ATT_BN * KPAD;
        const f16* Vt = Vsm + (jt & 1) * ATT_BN * VPAD;

        // S = Q K^T (log2 domain)
        float s[8][4];
        #pragma unroll
        for (int nt = 0; nt < 8; nt++)
            #pragma unroll
            for (int r = 0; r < 4; r++) s[nt][r] = 0.f;

        #pragma unroll
        for (int ks = 0; ks < 4; ks++) {
            const int kb = ks * 16 + 2 * tg;
            #pragma unroll
            for (int nt = 0; nt < 8; nt++) {
                const f16* kp = Kt + (nt * 8 + gID) * KPAD + kb;
                uint32_t bfr[2] = { *(const uint32_t*)kp, *(const uint32_t*)(kp + 8) };
                mma_f16(s[nt], qa[ks], bfr);
            }
        }

        // online softmax (rows gID / gID+8)
        float mx0 = s[0][0], mx1 = s[0][2];
        #pragma unroll
        for (int nt = 0; nt < 8; nt++) {
            mx0 = fmaxf(mx0, fmaxf(s[nt][0], s[nt][1]));
            mx1 = fmaxf(mx1, fmaxf(s[nt][2], s[nt][3]));
        }
        mx0 = fmaxf(mx0, __shfl_xor_sync(0xffffffffu, mx0, 1));
        mx0 = fmaxf(mx0, __shfl_xor_sync(0xffffffffu, mx0, 2));
        mx1 = fmaxf(mx1, __shfl_xor_sync(0xffffffffu, mx1, 1));
        mx1 = fmaxf(mx1, __shfl_xor_sync(0xffffffffu, mx1, 2));

        const float mn0 = fmaxf(m0, mx0), mn1 = fmaxf(m1, mx1);
        const float a0 = exp2f(m0 - mn0), a1 = exp2f(m1 - mn1);
        m0 = mn0; m1 = mn1;

        float ls0 = 0.f, ls1 = 0.f;
        #pragma unroll
        for (int nt = 0; nt < 8; nt++) {
            const float p0 = exp2f(s[nt][0] - m0);
            const float p1 = exp2f(s[nt][1] - m0);
            const float p2 = exp2f(s[nt][2] - m1);
            const float p3 = exp2f(s[nt][3] - m1);
            ls0 += p0 + p1;
            ls1 += p2 + p3;
            *(f162*)(Pw + gID * PPAD + nt * 8 + 2 * tg)       = __floats2half2_rn(p0, p1);
            *(f162*)(Pw + (gID + 8) * PPAD + nt * 8 + 2 * tg) = __floats2half2_rn(p2, p3);
            o[nt][0] *= a0; o[nt][1] *= a0;
            o[nt][2] *= a1; o[nt][3] *= a1;
        }
        l0 = l0 * a0 + ls0;
        l1 = l1 * a1 + ls1;
        __syncwarp();

        // O += P V  (contraction over keys, 4 x k16)
        #pragma unroll
        for (int ks = 0; ks < 4; ks++) {
            const int k0 = ks * 16 + 2 * tg;
            uint32_t pa[4];
            pa[0] = *(const uint32_t*)(Pw + gID * PPAD + k0);
            pa[1] = *(const uint32_t*)(Pw + (gID + 8) * PPAD + k0);
            pa[2] = *(const uint32_t*)(Pw + gID * PPAD + k0 + 8);
            pa[3] = *(const uint32_t*)(Pw + (gID + 8) * PPAD + k0 + 8);
            #pragma unroll
            for (int nt = 0; nt < 8; nt++) {
                const int d = nt * 8 + gID;
                uint32_t bfr[2];
                bfr[0] = pack_h2(Vt[(size_t)k0 * VPAD + d],       Vt[(size_t)(k0 + 1) * VPAD + d]);
                bfr[1] = pack_h2(Vt[(size_t)(k0 + 8) * VPAD + d], Vt[(size_t)(k0 + 9) * VPAD + d]);
                mma_f16(o[nt], pa, bfr);
            }
        }
        __syncwarp();
    }

    // finalize
    l0 += __shfl_xor_sync(0xffffffffu, l0, 1);
    l0 += __shfl_xor_sync(0xffffffffu, l0, 2);
    l1 += __shfl_xor_sync(0xffffffffu, l1, 1);
    l1 += __shfl_xor_sync(0xffffffffu, l1, 2);
    const float inv0 = 1.0f / l0, inv1 = 1.0f / l1;

    const int r0 = b * SEQ + q0 + wrow + gID;
    const int r1 = r0 + 8;
    f16* O0 = O + (size_t)r0 * DMODEL + h * DHEAD + 2 * tg;
    f16* O1 = O + (size_t)r1 * DMODEL + h * DHEAD + 2 * tg;
    #pragma unroll
    for (int nt = 0; nt < 8; nt++) {
        *(f162*)(O0 + nt * 8) = __floats2half2_rn(o[nt][0] * inv0, o[nt][1] * inv0);
        *(f162*)(O1 + nt * 8) = __floats2half2_rn(o[nt][2] * inv1, o[nt][3] * inv1);
    }
}

// ------------------------------- launcher ----------------------------------
extern "C" void kernel_launch(void* const* d_in, const int* in_sizes, int n_in,
                              void* d_out, int out_size)
{
    const float* src   = (const float*)d_in[0];
    const float* Wq    = (const float*)d_in[1];
    const float* bq    = (const float*)d_in[2];
    const float* Wk    = (const float*)d_in[3];
    const float* bk    = (const float*)d_in[4];
    const float* Wv    = (const float*)d_in[5];
    const float* bv    = (const float*)d_in[6];
    const float* Wo    = (const float*)d_in[7];
    const float* bo    = (const float*)d_in[8];
    const float* W1    = (const float*)d_in[9];
    const float* b1    = (const float*)d_in[10];
    const float* W2    = (const float*)d_in[11];
    const float* b2    = (const float*)d_in[12];
    const float* g1    = (const float*)d_in[13];
    const float* beta1 = (const float*)d_in[14];
    const float* g2    = (const float*)d_in[15];
    const float* beta2 = (const float*)d_in[16];
    float* out = (float*)d_out;

    f16 *x, *qkv, *ctx, *y, *hbuf, *wqkvT, *woT, *w1T, *w2T;
    float *bqkv;
    cudaGetSymbolAddress((void**)&x,     g_x);
    cudaGetSymbolAddress((void**)&qkv,   g_qkv);
    cudaGetSymbolAddress((void**)&ctx,   g_ctx);
    cudaGetSymbolAddress((void**)&y,     g_y);
    cudaGetSymbolAddress((void**)&hbuf,  g_h);
    cudaGetSymbolAddress((void**)&wqkvT, g_wqkvT);
    cudaGetSymbolAddress((void**)&bqkv,  g_bqkv);
    cudaGetSymbolAddress((void**)&woT,   g_woT);
    cudaGetSymbolAddress((void**)&w1T,   g_w1T);
    cudaGetSymbolAddress((void**)&w2T,   g_w2T);

    cudaFuncSetAttribute(f16_gemm_kernel<false,false,true>,
        cudaFuncAttributeMaxDynamicSharedMemorySize, GEMM_SMEM_BYTES);
    cudaFuncSetAttribute(f16_gemm_kernel<false,true,false>,
        cudaFuncAttributeMaxDynamicSharedMemorySize, GEMM_SMEM_BYTES);
    cudaFuncSetAttribute(f16_gemm_kernel<true,false,true>,
        cudaFuncAttributeMaxDynamicSharedMemorySize, GEMM_SMEM_BYTES);
    cudaFuncSetAttribute(mma_attn_kernel,
        cudaFuncAttributeMaxDynamicSharedMemorySize, ATT_SMEM_BYTES);

    // 0) weight transposes+convert ([K,N] fp32 -> [N,K] fp16), bias pack
    transpose_f16_kernel<<<dim3(DMODEL/32, DMODEL/32), 256>>>(Wq, wqkvT,                   DMODEL, DMODEL);
    transpose_f16_kernel<<<dim3(DMODEL/32, DMODEL/32), 256>>>(Wk, wqkvT + DMODEL*DMODEL,   DMODEL, DMODEL);
    transpose_f16_kernel<<<dim3(DMODEL/32, DMODEL/32), 256>>>(Wv, wqkvT + 2*DMODEL*DMODEL, DMODEL, DMODEL);
    transpose_f16_kernel<<<dim3(DMODEL/32, DMODEL/32), 256>>>(Wo, woT,                     DMODEL, DMODEL);
    transpose_f16_kernel<<<dim3(DFF/32,    DMODEL/32), 256>>>(W1, w1T, DMODEL, DFF);
    transpose_f16_kernel<<<dim3(DMODEL/32, DFF/32),    256>>>(W2, w2T, DFF, DMODEL);
    pack_bias_kernel<<<(3 * DMODEL + 255) / 256, 256>>>(bq, bk, bv, bqkv);

    // 1) LN1 -> fp16
    ln_kernel<<<NTOK, 256>>>(src, g1, beta1, x);

    // 2) fused QKV projection -> fp16
    {
        dim3 g(3 * DMODEL / 128, NTOK / 128);   // (24, 64)
        f16_gemm_kernel<false,false,true><<<g, 256, GEMM_SMEM_BYTES>>>(
            x, wqkvT, bqkv, nullptr, qkv, 3 * DMODEL, DMODEL);
    }

    // 3) attention (fp16 mma flash) -> ctx fp16
    {
        dim3 g(SEQ / ATT_BM, NHEAD, BATCH);     // (8,16,8)
        mma_attn_kernel<<<g, 256, ATT_SMEM_BYTES>>>(qkv, ctx);
    }

    // 4) output projection + residual -> d_out (fp32)
    {
        dim3 g(DMODEL / 128, NTOK / 128);
        f16_gemm_kernel<false,true,false><<<g, 256, GEMM_SMEM_BYTES>>>(
            ctx, woT, bo, src, out, DMODEL, DMODEL);
    }

    // 5) LN2 -> fp16
    ln_kernel<<<NTOK, 256>>>(out, g2, beta2, y);

    // 6) FFN up + ReLU -> fp16 hidden
    {
        dim3 g(DFF / 128, NTOK / 128);
        f16_gemm_kernel<true,false,true><<<g, 256, GEMM_SMEM_BYTES>>>(
            y, w1T, b1, nullptr, hbuf, DFF, DMODEL);
    }

    // 7) FFN down + bias + residual (in-place on d_out, fp32)
    {
        dim3 g(DMODEL / 128, NTOK / 128);
        f16_gemm_kernel<false,true,false><<<g, 256, GEMM_SMEM_BYTES>>>(
            hbuf, w2T, b2, out, out, DMODEL, DFF);
    }
}